// round 5
// baseline (speedup 1.0000x reference)
#include <cuda_runtime.h>
#include <math.h>
#include <stdint.h>

// ---------------------------------------------------------------------------
// Problem dims (fixed by the reference)
// ---------------------------------------------------------------------------
#define SEQ    2048
#define BATCH  32
#define DIM    1024
#define M_TOT  (SEQ * BATCH)     // 65536
#define N_TOT  (3 * DIM)         // 3072
#define K_TOT  DIM               // 1024

// GEMM tile
#define BM 128
#define BN 256
#define BK 32
#define NCHUNK (K_TOT / BK)      // 32
#define NSTAGE 3
#define ASTRIDE 36               // floats per SMEM row (32 + 4 pad): LDS banks
                                 // (36q + r)%32 = (4q+r)%32 all-distinct

// SMEM layout (bytes)
#define A_STG_BYTES (BM * ASTRIDE * 4)          // 18432
#define B_STG_BYTES (BN * ASTRIDE * 4)          // 36864
#define SMEM_B_BASE (NSTAGE * A_STG_BYTES)      // 55296
#define SMEM_BYTES  (SMEM_B_BASE + NSTAGE * B_STG_BYTES)  // 165888

// Scratch (device globals; no cudaMalloc allowed)
__device__ float g_act[(size_t)M_TOT * N_TOT];   // 768 MB activated gates
__device__ float g_Xr[(size_t)M_TOT * K_TOT];    // 256 MB tf32-rounded X
__device__ float g_Wr[(size_t)N_TOT * K_TOT];    // 12  MB tf32-rounded W

// ---------------------------------------------------------------------------
// Helpers
// ---------------------------------------------------------------------------
__device__ __forceinline__ uint32_t smem_u32(const void* p) {
    uint32_t a;
    asm("{ .reg .u64 t; cvta.to.shared.u64 t, %1; cvt.u32.u64 %0, t; }"
        : "=r"(a) : "l"(p));
    return a;
}
__device__ __forceinline__ uint32_t tf32_rna(float x) {
    uint32_t r; asm("cvt.rna.tf32.f32 %0, %1;" : "=r"(r) : "f"(x)); return r;
}
__device__ __forceinline__ float rcp_fast(float x) {
    float r; asm("rcp.approx.f32 %0, %1;" : "=f"(r) : "f"(x)); return r;
}
__device__ __forceinline__ float sigmoid_f(float x) {
    return rcp_fast(1.0f + __expf(-x));
}
__device__ __forceinline__ float tanh_f(float x) {
    return 1.0f - 2.0f * rcp_fast(1.0f + __expf(2.0f * x));
}

__device__ __forceinline__ void cp_async16(uint32_t dst_smem, const void* src) {
    asm volatile("cp.async.cg.shared.global [%0], [%1], 16;"
                 :: "r"(dst_smem), "l"(src) : "memory");
}
__device__ __forceinline__ void cp_commit() {
    asm volatile("cp.async.commit_group;" ::: "memory");
}
template <int N>
__device__ __forceinline__ void cp_wait() {
    asm volatile("cp.async.wait_group %0;" :: "n"(N) : "memory");
}

// m16n8k8 tf32 HMMA (portable PTX, legal at compute_103)
__device__ __forceinline__ void mma_tf32(float* d,
                                         const uint32_t* a,
                                         const uint32_t* bb) {
    asm volatile(
        "mma.sync.aligned.m16n8k8.row.col.f32.tf32.tf32.f32 "
        "{%0,%1,%2,%3}, {%4,%5,%6,%7}, {%8,%9}, {%0,%1,%2,%3};\n"
        : "+f"(d[0]), "+f"(d[1]), "+f"(d[2]), "+f"(d[3])
        : "r"(a[0]), "r"(a[1]), "r"(a[2]), "r"(a[3]),
          "r"(bb[0]), "r"(bb[1]));
}

// ---------------------------------------------------------------------------
// Kernel 0: round fp32 -> tf32 (rna)
// ---------------------------------------------------------------------------
__global__ __launch_bounds__(256)
void round_tf32_kernel(const float* __restrict__ in, float* __restrict__ out, int n4)
{
    int i = blockIdx.x * blockDim.x + threadIdx.x;
    if (i >= n4) return;
    float4 v = ((const float4*)in)[i];
    float4 o;
    o.x = __uint_as_float(tf32_rna(v.x));
    o.y = __uint_as_float(tf32_rna(v.y));
    o.z = __uint_as_float(tf32_rna(v.z));
    o.w = __uint_as_float(tf32_rna(v.w));
    ((float4*)out)[i] = o;
}

// ---------------------------------------------------------------------------
// Kernel 1: cp.async 3-stage pipelined tf32 HMMA GEMM with register-level
// fragment double-buffering.  C = Xr @ Wr^T + b, fused activation -> g_act
//   256 threads = 8 warps in 2(M) x 4(N); warp tile 64x64 (4x8 m16n8k8 grid)
// ---------------------------------------------------------------------------
__global__ __launch_bounds__(256, 1)
void gemm_hmma_kernel(const float* __restrict__ b)
{
    extern __shared__ __align__(16) char smem[];
    const uint32_t sbase = smem_u32(smem);

    const int tid = threadIdx.x;
    const int wid = tid >> 5;
    const int lid = tid & 31;
    const int lq  = lid >> 2;   // 0..7
    const int lr  = lid & 3;    // 0..3

    const int wm = (wid >> 2) * 64;   // warp M offset: 0 / 64
    const int wn = (wid & 3) * 64;    // warp N offset: 0..192

    const int block_m = blockIdx.y * BM;
    const int block_n = blockIdx.x * BN;

    const float* Abase = g_Xr + (size_t)block_m * K_TOT;
    const float* Bbase = g_Wr + (size_t)block_n * K_TOT;

    float acc[4][8][4];
#pragma unroll
    for (int mt = 0; mt < 4; ++mt)
#pragma unroll
        for (int nt = 0; nt < 8; ++nt)
#pragma unroll
            for (int r = 0; r < 4; ++r) acc[mt][nt][r] = 0.0f;

    // ---- prologue: issue async loads for stages 0..NSTAGE-1 ----
#pragma unroll
    for (int p = 0; p < NSTAGE; ++p) {
        const int kcol = p * BK;
        const uint32_t a_s = sbase + p * A_STG_BYTES;
        const uint32_t b_s = sbase + SMEM_B_BASE + p * B_STG_BYTES;
#pragma unroll
        for (int i = 0; i < 4; ++i) {
            int pos = tid + i * 256;
            int r = pos >> 3, c4 = pos & 7;
            cp_async16(a_s + (uint32_t)(r * ASTRIDE + c4 * 4) * 4,
                       Abase + (size_t)r * K_TOT + kcol + c4 * 4);
        }
#pragma unroll
        for (int i = 0; i < 8; ++i) {
            int pos = tid + i * 256;
            int r = pos >> 3, c4 = pos & 7;
            cp_async16(b_s + (uint32_t)(r * ASTRIDE + c4 * 4) * 4,
                       Bbase + (size_t)r * K_TOT + kcol + c4 * 4);
        }
        cp_commit();
    }

    // per-thread fragment base offsets (k0 added per ks)
    const int a_frag_base = (wm + lq) * ASTRIDE + lr;
    const int b_frag_base = (wn + lq) * ASTRIDE + lr;

    uint32_t afrag[2][4][4], bfrag[2][8][2];

    for (int c = 0; c < NCHUNK; ++c) {
        const int buf = c % NSTAGE;
        cp_wait<NSTAGE - 1>();
        __syncthreads();

        const uint32_t* As = (const uint32_t*)(smem + buf * A_STG_BYTES);
        const uint32_t* Bs = (const uint32_t*)(smem + SMEM_B_BASE + buf * B_STG_BYTES);

        // load fragments for ks=0
#pragma unroll
        for (int mt = 0; mt < 4; ++mt) {
            int base = a_frag_base + mt * 16 * ASTRIDE;
            afrag[0][mt][0] = As[base];
            afrag[0][mt][1] = As[base + 8 * ASTRIDE];
            afrag[0][mt][2] = As[base + 4];
            afrag[0][mt][3] = As[base + 8 * ASTRIDE + 4];
        }
#pragma unroll
        for (int nt = 0; nt < 8; ++nt) {
            int base = b_frag_base + nt * 8 * ASTRIDE;
            bfrag[0][nt][0] = Bs[base];
            bfrag[0][nt][1] = Bs[base + 4];
        }

#pragma unroll
        for (int ks = 0; ks < 4; ++ks) {
            const int cur = ks & 1;
            const int nxt = cur ^ 1;
            // prefetch fragments for ks+1 while current MMAs run
            if (ks < 3) {
                const int k0 = (ks + 1) * 8;
#pragma unroll
                for (int mt = 0; mt < 4; ++mt) {
                    int base = a_frag_base + mt * 16 * ASTRIDE + k0;
                    afrag[nxt][mt][0] = As[base];
                    afrag[nxt][mt][1] = As[base + 8 * ASTRIDE];
                    afrag[nxt][mt][2] = As[base + 4];
                    afrag[nxt][mt][3] = As[base + 8 * ASTRIDE + 4];
                }
#pragma unroll
                for (int nt = 0; nt < 8; ++nt) {
                    int base = b_frag_base + nt * 8 * ASTRIDE + k0;
                    bfrag[nxt][nt][0] = Bs[base];
                    bfrag[nxt][nt][1] = Bs[base + 4];
                }
            }
#pragma unroll
            for (int mt = 0; mt < 4; ++mt)
#pragma unroll
                for (int nt = 0; nt < 8; ++nt)
                    mma_tf32(acc[mt][nt], afrag[cur][mt], bfrag[cur][nt]);
        }

        __syncthreads();   // all warps done reading buf before refill

        if (c + NSTAGE < NCHUNK) {
            const int kcol = (c + NSTAGE) * BK;
            const uint32_t a_s = sbase + buf * A_STG_BYTES;
            const uint32_t b_s = sbase + SMEM_B_BASE + buf * B_STG_BYTES;
#pragma unroll
            for (int i = 0; i < 4; ++i) {
                int pos = tid + i * 256;
                int r = pos >> 3, c4 = pos & 7;
                cp_async16(a_s + (uint32_t)(r * ASTRIDE + c4 * 4) * 4,
                           Abase + (size_t)r * K_TOT + kcol + c4 * 4);
            }
#pragma unroll
            for (int i = 0; i < 8; ++i) {
                int pos = tid + i * 256;
                int r = pos >> 3, c4 = pos & 7;
                cp_async16(b_s + (uint32_t)(r * ASTRIDE + c4 * 4) * 4,
                           Bbase + (size_t)r * K_TOT + kcol + c4 * 4);
            }
        }
        cp_commit();   // keep group accounting uniform
    }

    // ---- epilogue: bias + activation -> g_act ----
    const bool is_tanh = (block_n < DIM);   // BN=256 divides DIM

#pragma unroll
    for (int nt = 0; nt < 8; ++nt) {
        const int gc = block_n + wn + nt * 8 + 2 * lr;
        const float b0 = __ldg(&b[gc]);
        const float b1 = __ldg(&b[gc + 1]);
#pragma unroll
        for (int mt = 0; mt < 4; ++mt) {
            const int gm0 = block_m + wm + mt * 16 + lq;
            const int gm1 = gm0 + 8;
            float v00 = acc[mt][nt][0] + b0;
            float v01 = acc[mt][nt][1] + b1;
            float v10 = acc[mt][nt][2] + b0;
            float v11 = acc[mt][nt][3] + b1;
            float2 r0, r1;
            if (is_tanh) {
                r0.x = tanh_f(v00); r0.y = tanh_f(v01);
                r1.x = tanh_f(v10); r1.y = tanh_f(v11);
            } else {
                r0.x = sigmoid_f(v00); r0.y = sigmoid_f(v01);
                r1.x = sigmoid_f(v10); r1.y = sigmoid_f(v11);
            }
            *(float2*)(&g_act[(size_t)gm0 * N_TOT + gc]) = r0;
            *(float2*)(&g_act[(size_t)gm1 * N_TOT + gc]) = r1;
        }
    }
}

// ---------------------------------------------------------------------------
// Kernel 2: sequential scan — 4 chains per thread via float4, deep MLP.
//   8192 threads = 128 CTAs x 64 threads; thread t handles batch bb = t>>8,
//   features d = 4*(t&255) .. +3.
// ---------------------------------------------------------------------------
__global__ __launch_bounds__(64)
void scan_kernel(const float* __restrict__ hidden, float* __restrict__ out)
{
    const int t  = blockIdx.x * 64 + threadIdx.x;   // 0..8191
    const int bb = t >> 8;                          // 0..31
    const int dv = t & 255;                         // float4 index within DIM

    float4 h = ((const float4*)hidden)[bb * 256 + dv];

    float4* __restrict__ H4  = (float4*)out;
    float4* __restrict__ hn4 = (float4*)(out + (size_t)SEQ * BATCH * DIM);

    const float4* __restrict__ act4 = (const float4*)g_act;

#pragma unroll 4
    for (int s = 0; s < SEQ; ++s) {
        const size_t row4 = (size_t)(s * BATCH + bb) * (N_TOT / 4);
        const float4 z = act4[row4 + dv];
        const float4 f = act4[row4 + 256 + dv];
        const float4 o = act4[row4 + 512 + dv];
        h.x = fmaf(f.x, h.x - z.x, z.x);
        h.y = fmaf(f.y, h.y - z.y, z.y);
        h.z = fmaf(f.z, h.z - z.z, z.z);
        h.w = fmaf(f.w, h.w - z.w, z.w);
        float4 r;
        r.x = o.x * h.x; r.y = o.y * h.y; r.z = o.z * h.z; r.w = o.w * h.w;
        H4[(size_t)(s * BATCH + bb) * 256 + dv] = r;
    }
    hn4[bb * 256 + dv] = h;
}

// ---------------------------------------------------------------------------
extern "C" void kernel_launch(void* const* d_in, const int* in_sizes, int n_in,
                              void* d_out, int out_size)
{
    const float* X      = (const float*)d_in[0];   // [2048, 32, 1024]
    const float* hidden = (const float*)d_in[1];   // [1, 32, 1024]
    const float* W      = (const float*)d_in[2];   // [3072, 1024]
    const float* b      = (const float*)d_in[3];   // [3072]
    float* out = (float*)d_out;

    cudaFuncSetAttribute(gemm_hmma_kernel,
                         cudaFuncAttributeMaxDynamicSharedMemorySize,
                         SMEM_BYTES);

    float* Xr; float* Wr;
    cudaGetSymbolAddress((void**)&Xr, g_Xr);
    cudaGetSymbolAddress((void**)&Wr, g_Wr);

    // round inputs to tf32 (rna)
    {
        int n4x = (M_TOT * K_TOT) / 4;
        round_tf32_kernel<<<n4x / 256, 256>>>(X, Xr, n4x);
        int n4w = (N_TOT * K_TOT) / 4;
        round_tf32_kernel<<<n4w / 256, 256>>>(W, Wr, n4w);
    }

    dim3 grid(N_TOT / BN, M_TOT / BM);   // (12, 512)
    gemm_hmma_kernel<<<grid, 256, SMEM_BYTES>>>(b);

    scan_kernel<<<128, 64>>>(hidden, out);
}

// round 6
// speedup vs baseline: 1.0421x; 1.0421x over previous
#include <cuda_runtime.h>
#include <math.h>
#include <stdint.h>

// ---------------------------------------------------------------------------
// Problem dims (fixed by the reference)
// ---------------------------------------------------------------------------
#define SEQ    2048
#define BATCH  32
#define DIM    1024
#define M_TOT  (SEQ * BATCH)     // 65536
#define N_TOT  (3 * DIM)         // 3072
#define K_TOT  DIM               // 1024

// GEMM tile
#define BM 128
#define BN 256
#define BK 32
#define NCHUNK (K_TOT / BK)      // 32
#define NSTAGE 3
#define ASTRIDE 36               // floats per SMEM row (32 + 4 pad): LDS banks
                                 // (36q + r)%32 = (4q+r)%32 all-distinct

// SMEM layout (bytes)
#define A_STG_BYTES (BM * ASTRIDE * 4)          // 18432
#define B_STG_BYTES (BN * ASTRIDE * 4)          // 36864
#define SMEM_B_BASE (NSTAGE * A_STG_BYTES)      // 55296
#define SMEM_BYTES  (SMEM_B_BASE + NSTAGE * B_STG_BYTES)  // 165888

// Scratch (device globals; no cudaMalloc allowed)
__device__ float g_act[(size_t)M_TOT * N_TOT];   // 768 MB activated gates
__device__ float g_Xr[(size_t)M_TOT * K_TOT];    // 256 MB tf32-rounded X
__device__ float g_Wr[(size_t)N_TOT * K_TOT];    // 12  MB tf32-rounded W

// ---------------------------------------------------------------------------
// Helpers
// ---------------------------------------------------------------------------
__device__ __forceinline__ uint32_t smem_u32(const void* p) {
    uint32_t a;
    asm("{ .reg .u64 t; cvta.to.shared.u64 t, %1; cvt.u32.u64 %0, t; }"
        : "=r"(a) : "l"(p));
    return a;
}
__device__ __forceinline__ uint32_t tf32_rna(float x) {
    uint32_t r; asm("cvt.rna.tf32.f32 %0, %1;" : "=r"(r) : "f"(x)); return r;
}
__device__ __forceinline__ float rcp_fast(float x) {
    float r; asm("rcp.approx.f32 %0, %1;" : "=f"(r) : "f"(x)); return r;
}
__device__ __forceinline__ float sigmoid_f(float x) {
    return rcp_fast(1.0f + __expf(-x));
}
__device__ __forceinline__ float tanh_f(float x) {
    return 1.0f - 2.0f * rcp_fast(1.0f + __expf(2.0f * x));
}

__device__ __forceinline__ void cp_async16(uint32_t dst_smem, const void* src) {
    asm volatile("cp.async.cg.shared.global [%0], [%1], 16;"
                 :: "r"(dst_smem), "l"(src) : "memory");
}
__device__ __forceinline__ void cp_commit() {
    asm volatile("cp.async.commit_group;" ::: "memory");
}
template <int N>
__device__ __forceinline__ void cp_wait() {
    asm volatile("cp.async.wait_group %0;" :: "n"(N) : "memory");
}

// m16n8k8 tf32 HMMA (portable PTX, legal at compute_103)
__device__ __forceinline__ void mma_tf32(float* d,
                                         const uint32_t* a,
                                         const uint32_t* bb) {
    asm volatile(
        "mma.sync.aligned.m16n8k8.row.col.f32.tf32.tf32.f32 "
        "{%0,%1,%2,%3}, {%4,%5,%6,%7}, {%8,%9}, {%0,%1,%2,%3};\n"
        : "+f"(d[0]), "+f"(d[1]), "+f"(d[2]), "+f"(d[3])
        : "r"(a[0]), "r"(a[1]), "r"(a[2]), "r"(a[3]),
          "r"(bb[0]), "r"(bb[1]));
}

// ---------------------------------------------------------------------------
// Kernel 0: round fp32 -> tf32 (rna)
// ---------------------------------------------------------------------------
__global__ __launch_bounds__(256)
void round_tf32_kernel(const float* __restrict__ in, float* __restrict__ out, int n4)
{
    int i = blockIdx.x * blockDim.x + threadIdx.x;
    if (i >= n4) return;
    float4 v = ((const float4*)in)[i];
    float4 o;
    o.x = __uint_as_float(tf32_rna(v.x));
    o.y = __uint_as_float(tf32_rna(v.y));
    o.z = __uint_as_float(tf32_rna(v.z));
    o.w = __uint_as_float(tf32_rna(v.w));
    ((float4*)out)[i] = o;
}

// ---------------------------------------------------------------------------
// Kernel 1: cp.async 3-stage pipelined tf32 HMMA GEMM (R4 mainloop, known-good)
//   C = Xr @ Wr^T + b, fused activation -> g_act
//   256 threads = 8 warps in 2(M) x 4(N); warp tile 64x64 (4x8 m16n8k8 grid)
// ---------------------------------------------------------------------------
__global__ __launch_bounds__(256, 1)
void gemm_hmma_kernel(const float* __restrict__ b)
{
    extern __shared__ __align__(16) char smem[];
    const uint32_t sbase = smem_u32(smem);

    const int tid = threadIdx.x;
    const int wid = tid >> 5;
    const int lid = tid & 31;
    const int lq  = lid >> 2;   // 0..7
    const int lr  = lid & 3;    // 0..3

    const int wm = (wid >> 2) * 64;   // warp M offset: 0 / 64
    const int wn = (wid & 3) * 64;    // warp N offset: 0..192

    const int block_m = blockIdx.y * BM;
    const int block_n = blockIdx.x * BN;

    const float* Abase = g_Xr + (size_t)block_m * K_TOT;
    const float* Bbase = g_Wr + (size_t)block_n * K_TOT;

    float acc[4][8][4];
#pragma unroll
    for (int mt = 0; mt < 4; ++mt)
#pragma unroll
        for (int nt = 0; nt < 8; ++nt)
#pragma unroll
            for (int r = 0; r < 4; ++r) acc[mt][nt][r] = 0.0f;

    // ---- prologue: issue async loads for stages 0..NSTAGE-1 ----
#pragma unroll
    for (int p = 0; p < NSTAGE; ++p) {
        const int kcol = p * BK;
        const uint32_t a_s = sbase + p * A_STG_BYTES;
        const uint32_t b_s = sbase + SMEM_B_BASE + p * B_STG_BYTES;
#pragma unroll
        for (int i = 0; i < 4; ++i) {
            int pos = tid + i * 256;
            int r = pos >> 3, c4 = pos & 7;
            cp_async16(a_s + (uint32_t)(r * ASTRIDE + c4 * 4) * 4,
                       Abase + (size_t)r * K_TOT + kcol + c4 * 4);
        }
#pragma unroll
        for (int i = 0; i < 8; ++i) {
            int pos = tid + i * 256;
            int r = pos >> 3, c4 = pos & 7;
            cp_async16(b_s + (uint32_t)(r * ASTRIDE + c4 * 4) * 4,
                       Bbase + (size_t)r * K_TOT + kcol + c4 * 4);
        }
        cp_commit();
    }

    for (int c = 0; c < NCHUNK; ++c) {
        const int buf = c % NSTAGE;
        cp_wait<NSTAGE - 1>();
        __syncthreads();

        const uint32_t* As = (const uint32_t*)(smem + buf * A_STG_BYTES);
        const uint32_t* Bs = (const uint32_t*)(smem + SMEM_B_BASE + buf * B_STG_BYTES);

#pragma unroll
        for (int ks = 0; ks < 4; ++ks) {
            const int k0 = ks * 8;
            uint32_t afrag[4][4], bfrag[8][2];
#pragma unroll
            for (int mt = 0; mt < 4; ++mt) {
                int base = (wm + mt * 16 + lq) * ASTRIDE + k0 + lr;
                afrag[mt][0] = As[base];
                afrag[mt][1] = As[base + 8 * ASTRIDE];
                afrag[mt][2] = As[base + 4];
                afrag[mt][3] = As[base + 8 * ASTRIDE + 4];
            }
#pragma unroll
            for (int nt = 0; nt < 8; ++nt) {
                int base = (wn + nt * 8 + lq) * ASTRIDE + k0 + lr;
                bfrag[nt][0] = Bs[base];
                bfrag[nt][1] = Bs[base + 4];
            }
#pragma unroll
            for (int mt = 0; mt < 4; ++mt)
#pragma unroll
                for (int nt = 0; nt < 8; ++nt)
                    mma_tf32(acc[mt][nt], afrag[mt], bfrag[nt]);
        }

        __syncthreads();   // all warps done reading buf before refill

        if (c + NSTAGE < NCHUNK) {
            const int kcol = (c + NSTAGE) * BK;
            const uint32_t a_s = sbase + buf * A_STG_BYTES;
            const uint32_t b_s = sbase + SMEM_B_BASE + buf * B_STG_BYTES;
#pragma unroll
            for (int i = 0; i < 4; ++i) {
                int pos = tid + i * 256;
                int r = pos >> 3, c4 = pos & 7;
                cp_async16(a_s + (uint32_t)(r * ASTRIDE + c4 * 4) * 4,
                           Abase + (size_t)r * K_TOT + kcol + c4 * 4);
            }
#pragma unroll
            for (int i = 0; i < 8; ++i) {
                int pos = tid + i * 256;
                int r = pos >> 3, c4 = pos & 7;
                cp_async16(b_s + (uint32_t)(r * ASTRIDE + c4 * 4) * 4,
                           Bbase + (size_t)r * K_TOT + kcol + c4 * 4);
            }
        }
        cp_commit();   // keep group accounting uniform
    }

    // ---- epilogue: bias + activation -> g_act ----
    const bool is_tanh = (block_n < DIM);   // BN=256 divides DIM

#pragma unroll
    for (int nt = 0; nt < 8; ++nt) {
        const int gc = block_n + wn + nt * 8 + 2 * lr;
        const float b0 = __ldg(&b[gc]);
        const float b1 = __ldg(&b[gc + 1]);
#pragma unroll
        for (int mt = 0; mt < 4; ++mt) {
            const int gm0 = block_m + wm + mt * 16 + lq;
            const int gm1 = gm0 + 8;
            float v00 = acc[mt][nt][0] + b0;
            float v01 = acc[mt][nt][1] + b1;
            float v10 = acc[mt][nt][2] + b0;
            float v11 = acc[mt][nt][3] + b1;
            float2 r0, r1;
            if (is_tanh) {
                r0.x = tanh_f(v00); r0.y = tanh_f(v01);
                r1.x = tanh_f(v10); r1.y = tanh_f(v11);
            } else {
                r0.x = sigmoid_f(v00); r0.y = sigmoid_f(v01);
                r1.x = sigmoid_f(v10); r1.y = sigmoid_f(v11);
            }
            *(float2*)(&g_act[(size_t)gm0 * N_TOT + gc]) = r0;
            *(float2*)(&g_act[(size_t)gm1 * N_TOT + gc]) = r1;
        }
    }
}

// ---------------------------------------------------------------------------
// Kernel 2: sequential scan — float4 chains with explicit one-step prefetch.
//   8192 threads = 128 CTAs x 64; thread handles batch bb = t>>8, float4 dv.
//   __ldg prefetch of s+1's gates issues 3 LDG.128 ahead of the serial FMA
//   chain, decoupling loads from the h dependency and the output stores.
// ---------------------------------------------------------------------------
__global__ __launch_bounds__(64)
void scan_kernel(const float* __restrict__ hidden, float* __restrict__ out)
{
    const int t  = blockIdx.x * 64 + threadIdx.x;   // 0..8191
    const int bb = t >> 8;                          // 0..31
    const int dv = t & 255;                         // float4 index within DIM

    float4 h = __ldg(&((const float4*)hidden)[bb * 256 + dv]);

    float4* __restrict__ H4  = (float4*)out;
    float4* __restrict__ hn4 = (float4*)(out + (size_t)SEQ * BATCH * DIM);

    const float4* __restrict__ act4 = (const float4*)g_act;

    // prefetch s=0
    size_t row4 = (size_t)bb * (N_TOT / 4);
    float4 z = __ldg(&act4[row4 + dv]);
    float4 f = __ldg(&act4[row4 + 256 + dv]);
    float4 o = __ldg(&act4[row4 + 512 + dv]);

#pragma unroll 4
    for (int s = 0; s < SEQ; ++s) {
        float4 zn, fn, on;
        if (s + 1 < SEQ) {
            const size_t nrow4 = (size_t)((s + 1) * BATCH + bb) * (N_TOT / 4);
            zn = __ldg(&act4[nrow4 + dv]);
            fn = __ldg(&act4[nrow4 + 256 + dv]);
            on = __ldg(&act4[nrow4 + 512 + dv]);
        }
        h.x = fmaf(f.x, h.x - z.x, z.x);
        h.y = fmaf(f.y, h.y - z.y, z.y);
        h.z = fmaf(f.z, h.z - z.z, z.z);
        h.w = fmaf(f.w, h.w - z.w, z.w);
        float4 r;
        r.x = o.x * h.x; r.y = o.y * h.y; r.z = o.z * h.z; r.w = o.w * h.w;
        H4[(size_t)(s * BATCH + bb) * 256 + dv] = r;
        z = zn; f = fn; o = on;
    }
    hn4[bb * 256 + dv] = h;
}

// ---------------------------------------------------------------------------
extern "C" void kernel_launch(void* const* d_in, const int* in_sizes, int n_in,
                              void* d_out, int out_size)
{
    const float* X      = (const float*)d_in[0];   // [2048, 32, 1024]
    const float* hidden = (const float*)d_in[1];   // [1, 32, 1024]
    const float* W      = (const float*)d_in[2];   // [3072, 1024]
    const float* b      = (const float*)d_in[3];   // [3072]
    float* out = (float*)d_out;

    cudaFuncSetAttribute(gemm_hmma_kernel,
                         cudaFuncAttributeMaxDynamicSharedMemorySize,
                         SMEM_BYTES);

    float* Xr; float* Wr;
    cudaGetSymbolAddress((void**)&Xr, g_Xr);
    cudaGetSymbolAddress((void**)&Wr, g_Wr);

    // round inputs to tf32 (rna)
    {
        int n4x = (M_TOT * K_TOT) / 4;
        round_tf32_kernel<<<n4x / 256, 256>>>(X, Xr, n4x);
        int n4w = (N_TOT * K_TOT) / 4;
        round_tf32_kernel<<<n4w / 256, 256>>>(W, Wr, n4w);
    }

    dim3 grid(N_TOT / BN, M_TOT / BM);   // (12, 512)
    gemm_hmma_kernel<<<grid, 256, SMEM_BYTES>>>(b);

    scan_kernel<<<128, 64>>>(hidden, out);
}

// round 7
// speedup vs baseline: 1.0866x; 1.0426x over previous
#include <cuda_runtime.h>
#include <math.h>
#include <stdint.h>

// ---------------------------------------------------------------------------
// Problem dims (fixed by the reference)
// ---------------------------------------------------------------------------
#define SEQ    2048
#define BATCH  32
#define DIM    1024
#define M_TOT  (SEQ * BATCH)     // 65536
#define N_TOT  (3 * DIM)         // 3072
#define K_TOT  DIM               // 1024

// GEMM tile
#define BM 128
#define BN 256
#define BK 32
#define NCHUNK (K_TOT / BK)      // 32
#define NSTAGE 3
#define ASTRIDE 36               // floats per SMEM row (32 + 4 pad): LDS banks
                                 // (36q + r)%32 = (4q+r)%32 all-distinct

// SMEM layout (bytes)
#define A_STG_BYTES (BM * ASTRIDE * 4)          // 18432
#define B_STG_BYTES (BN * ASTRIDE * 4)          // 36864
#define SMEM_B_BASE (NSTAGE * A_STG_BYTES)      // 55296
#define SMEM_BYTES  (SMEM_B_BASE + NSTAGE * B_STG_BYTES)  // 165888

// Scratch (device globals; no cudaMalloc allowed)
__device__ float g_act[(size_t)M_TOT * N_TOT];   // 768 MB activated gates
__device__ float g_Xr[(size_t)M_TOT * K_TOT];    // 256 MB tf32-rounded X
__device__ float g_Wr[(size_t)N_TOT * K_TOT];    // 12  MB tf32-rounded W

// ---------------------------------------------------------------------------
// Helpers
// ---------------------------------------------------------------------------
__device__ __forceinline__ uint32_t smem_u32(const void* p) {
    uint32_t a;
    asm("{ .reg .u64 t; cvta.to.shared.u64 t, %1; cvt.u32.u64 %0, t; }"
        : "=r"(a) : "l"(p));
    return a;
}
__device__ __forceinline__ uint32_t tf32_rna(float x) {
    uint32_t r; asm("cvt.rna.tf32.f32 %0, %1;" : "=r"(r) : "f"(x)); return r;
}
__device__ __forceinline__ float rcp_fast(float x) {
    float r; asm("rcp.approx.f32 %0, %1;" : "=f"(r) : "f"(x)); return r;
}
__device__ __forceinline__ float sigmoid_f(float x) {
    return rcp_fast(1.0f + __expf(-x));
}
__device__ __forceinline__ float tanh_f(float x) {
    return 1.0f - 2.0f * rcp_fast(1.0f + __expf(2.0f * x));
}

__device__ __forceinline__ void cp_async16(uint32_t dst_smem, const void* src) {
    asm volatile("cp.async.cg.shared.global [%0], [%1], 16;"
                 :: "r"(dst_smem), "l"(src) : "memory");
}
__device__ __forceinline__ void cp_commit() {
    asm volatile("cp.async.commit_group;" ::: "memory");
}
template <int N>
__device__ __forceinline__ void cp_wait() {
    asm volatile("cp.async.wait_group %0;" :: "n"(N) : "memory");
}

// m16n8k8 tf32 HMMA (portable PTX, legal at compute_103)
__device__ __forceinline__ void mma_tf32(float* d,
                                         const uint32_t* a,
                                         const uint32_t* bb) {
    asm volatile(
        "mma.sync.aligned.m16n8k8.row.col.f32.tf32.tf32.f32 "
        "{%0,%1,%2,%3}, {%4,%5,%6,%7}, {%8,%9}, {%0,%1,%2,%3};\n"
        : "+f"(d[0]), "+f"(d[1]), "+f"(d[2]), "+f"(d[3])
        : "r"(a[0]), "r"(a[1]), "r"(a[2]), "r"(a[3]),
          "r"(bb[0]), "r"(bb[1]));
}

// ---------------------------------------------------------------------------
// Kernel 0: round fp32 -> tf32 (rna)
// ---------------------------------------------------------------------------
__global__ __launch_bounds__(256)
void round_tf32_kernel(const float* __restrict__ in, float* __restrict__ out, int n4)
{
    int i = blockIdx.x * blockDim.x + threadIdx.x;
    if (i >= n4) return;
    float4 v = ((const float4*)in)[i];
    float4 o;
    o.x = __uint_as_float(tf32_rna(v.x));
    o.y = __uint_as_float(tf32_rna(v.y));
    o.z = __uint_as_float(tf32_rna(v.z));
    o.w = __uint_as_float(tf32_rna(v.w));
    ((float4*)out)[i] = o;
}

// ---------------------------------------------------------------------------
// Kernel 1: cp.async 3-stage pipelined tf32 HMMA GEMM (R4 mainloop, known-good)
//   C = Xr @ Wr^T + b, fused activation -> g_act
//   256 threads = 8 warps in 2(M) x 4(N); warp tile 64x64 (4x8 m16n8k8 grid)
// ---------------------------------------------------------------------------
__global__ __launch_bounds__(256, 1)
void gemm_hmma_kernel(const float* __restrict__ b)
{
    extern __shared__ __align__(16) char smem[];
    const uint32_t sbase = smem_u32(smem);

    const int tid = threadIdx.x;
    const int wid = tid >> 5;
    const int lid = tid & 31;
    const int lq  = lid >> 2;   // 0..7
    const int lr  = lid & 3;    // 0..3

    const int wm = (wid >> 2) * 64;   // warp M offset: 0 / 64
    const int wn = (wid & 3) * 64;    // warp N offset: 0..192

    const int block_m = blockIdx.y * BM;
    const int block_n = blockIdx.x * BN;

    const float* Abase = g_Xr + (size_t)block_m * K_TOT;
    const float* Bbase = g_Wr + (size_t)block_n * K_TOT;

    float acc[4][8][4];
#pragma unroll
    for (int mt = 0; mt < 4; ++mt)
#pragma unroll
        for (int nt = 0; nt < 8; ++nt)
#pragma unroll
            for (int r = 0; r < 4; ++r) acc[mt][nt][r] = 0.0f;

    // ---- prologue: issue async loads for stages 0..NSTAGE-1 ----
#pragma unroll
    for (int p = 0; p < NSTAGE; ++p) {
        const int kcol = p * BK;
        const uint32_t a_s = sbase + p * A_STG_BYTES;
        const uint32_t b_s = sbase + SMEM_B_BASE + p * B_STG_BYTES;
#pragma unroll
        for (int i = 0; i < 4; ++i) {
            int pos = tid + i * 256;
            int r = pos >> 3, c4 = pos & 7;
            cp_async16(a_s + (uint32_t)(r * ASTRIDE + c4 * 4) * 4,
                       Abase + (size_t)r * K_TOT + kcol + c4 * 4);
        }
#pragma unroll
        for (int i = 0; i < 8; ++i) {
            int pos = tid + i * 256;
            int r = pos >> 3, c4 = pos & 7;
            cp_async16(b_s + (uint32_t)(r * ASTRIDE + c4 * 4) * 4,
                       Bbase + (size_t)r * K_TOT + kcol + c4 * 4);
        }
        cp_commit();
    }

    for (int c = 0; c < NCHUNK; ++c) {
        const int buf = c % NSTAGE;
        cp_wait<NSTAGE - 1>();
        __syncthreads();

        const uint32_t* As = (const uint32_t*)(smem + buf * A_STG_BYTES);
        const uint32_t* Bs = (const uint32_t*)(smem + SMEM_B_BASE + buf * B_STG_BYTES);

#pragma unroll
        for (int ks = 0; ks < 4; ++ks) {
            const int k0 = ks * 8;
            uint32_t afrag[4][4], bfrag[8][2];
#pragma unroll
            for (int mt = 0; mt < 4; ++mt) {
                int base = (wm + mt * 16 + lq) * ASTRIDE + k0 + lr;
                afrag[mt][0] = As[base];
                afrag[mt][1] = As[base + 8 * ASTRIDE];
                afrag[mt][2] = As[base + 4];
                afrag[mt][3] = As[base + 8 * ASTRIDE + 4];
            }
#pragma unroll
            for (int nt = 0; nt < 8; ++nt) {
                int base = (wn + nt * 8 + lq) * ASTRIDE + k0 + lr;
                bfrag[nt][0] = Bs[base];
                bfrag[nt][1] = Bs[base + 4];
            }
#pragma unroll
            for (int mt = 0; mt < 4; ++mt)
#pragma unroll
                for (int nt = 0; nt < 8; ++nt)
                    mma_tf32(acc[mt][nt], afrag[mt], bfrag[nt]);
        }

        __syncthreads();   // all warps done reading buf before refill

        if (c + NSTAGE < NCHUNK) {
            const int kcol = (c + NSTAGE) * BK;
            const uint32_t a_s = sbase + buf * A_STG_BYTES;
            const uint32_t b_s = sbase + SMEM_B_BASE + buf * B_STG_BYTES;
#pragma unroll
            for (int i = 0; i < 4; ++i) {
                int pos = tid + i * 256;
                int r = pos >> 3, c4 = pos & 7;
                cp_async16(a_s + (uint32_t)(r * ASTRIDE + c4 * 4) * 4,
                           Abase + (size_t)r * K_TOT + kcol + c4 * 4);
            }
#pragma unroll
            for (int i = 0; i < 8; ++i) {
                int pos = tid + i * 256;
                int r = pos >> 3, c4 = pos & 7;
                cp_async16(b_s + (uint32_t)(r * ASTRIDE + c4 * 4) * 4,
                           Bbase + (size_t)r * K_TOT + kcol + c4 * 4);
            }
        }
        cp_commit();   // keep group accounting uniform
    }

    // ---- epilogue: bias + activation -> g_act ----
    const bool is_tanh = (block_n < DIM);   // BN=256 divides DIM

#pragma unroll
    for (int nt = 0; nt < 8; ++nt) {
        const int gc = block_n + wn + nt * 8 + 2 * lr;
        const float b0 = __ldg(&b[gc]);
        const float b1 = __ldg(&b[gc + 1]);
#pragma unroll
        for (int mt = 0; mt < 4; ++mt) {
            const int gm0 = block_m + wm + mt * 16 + lq;
            const int gm1 = gm0 + 8;
            float v00 = acc[mt][nt][0] + b0;
            float v01 = acc[mt][nt][1] + b1;
            float v10 = acc[mt][nt][2] + b0;
            float v11 = acc[mt][nt][3] + b1;
            float2 r0, r1;
            if (is_tanh) {
                r0.x = tanh_f(v00); r0.y = tanh_f(v01);
                r1.x = tanh_f(v10); r1.y = tanh_f(v11);
            } else {
                r0.x = sigmoid_f(v00); r0.y = sigmoid_f(v01);
                r1.x = sigmoid_f(v10); r1.y = sigmoid_f(v11);
            }
            *(float2*)(&g_act[(size_t)gm0 * N_TOT + gc]) = r0;
            *(float2*)(&g_act[(size_t)gm1 * N_TOT + gc]) = r1;
        }
    }
}

// ---------------------------------------------------------------------------
// Kernel 2: sequential scan — R4 layout (32768 scalar chains, 256 CTAs x 128
// threads = ~7 warps/SM) + explicit distance-2 __ldg prefetch so each thread
// keeps ~6 independent loads in flight ahead of the serial FMA chain.
// ---------------------------------------------------------------------------
__global__ __launch_bounds__(128)
void scan_kernel(const float* __restrict__ hidden, float* __restrict__ out)
{
    const int t  = blockIdx.x * 128 + threadIdx.x;  // 0..32767
    const int bb = t >> 10;                         // batch index
    const int d  = t & 1023;                        // feature index

    float h = __ldg(&hidden[bb * DIM + d]);

    float* __restrict__ Hout = out;
    float* __restrict__ hn   = out + (size_t)SEQ * BATCH * DIM;

    const float* __restrict__ act = g_act;

    // prefetch s=0 and s=1
    size_t r0 = (size_t)(0 * BATCH + bb) * N_TOT;
    size_t r1 = (size_t)(1 * BATCH + bb) * N_TOT;
    float z0 = __ldg(&act[r0 + d]);
    float f0 = __ldg(&act[r0 + DIM + d]);
    float o0 = __ldg(&act[r0 + 2 * DIM + d]);
    float z1 = __ldg(&act[r1 + d]);
    float f1 = __ldg(&act[r1 + DIM + d]);
    float o1 = __ldg(&act[r1 + 2 * DIM + d]);

#pragma unroll 4
    for (int s = 0; s < SEQ; ++s) {
        // prefetch s+2
        float z2, f2, o2;
        if (s + 2 < SEQ) {
            const size_t r2 = (size_t)((s + 2) * BATCH + bb) * N_TOT;
            z2 = __ldg(&act[r2 + d]);
            f2 = __ldg(&act[r2 + DIM + d]);
            o2 = __ldg(&act[r2 + 2 * DIM + d]);
        }
        h = fmaf(f0, h - z0, z0);
        Hout[(size_t)(s * BATCH + bb) * DIM + d] = o0 * h;
        // rotate
        z0 = z1; f0 = f1; o0 = o1;
        z1 = z2; f1 = f2; o1 = o2;
    }
    hn[bb * DIM + d] = h;
}

// ---------------------------------------------------------------------------
extern "C" void kernel_launch(void* const* d_in, const int* in_sizes, int n_in,
                              void* d_out, int out_size)
{
    const float* X      = (const float*)d_in[0];   // [2048, 32, 1024]
    const float* hidden = (const float*)d_in[1];   // [1, 32, 1024]
    const float* W      = (const float*)d_in[2];   // [3072, 1024]
    const float* b      = (const float*)d_in[3];   // [3072]
    float* out = (float*)d_out;

    cudaFuncSetAttribute(gemm_hmma_kernel,
                         cudaFuncAttributeMaxDynamicSharedMemorySize,
                         SMEM_BYTES);

    float* Xr; float* Wr;
    cudaGetSymbolAddress((void**)&Xr, g_Xr);
    cudaGetSymbolAddress((void**)&Wr, g_Wr);

    // round inputs to tf32 (rna)
    {
        int n4x = (M_TOT * K_TOT) / 4;
        round_tf32_kernel<<<n4x / 256, 256>>>(X, Xr, n4x);
        int n4w = (N_TOT * K_TOT) / 4;
        round_tf32_kernel<<<n4w / 256, 256>>>(W, Wr, n4w);
    }

    dim3 grid(N_TOT / BN, M_TOT / BM);   // (12, 512)
    gemm_hmma_kernel<<<grid, 256, SMEM_BYTES>>>(b);

    scan_kernel<<<(BATCH * DIM) / 128, 128>>>(hidden, out);
}

// round 8
// speedup vs baseline: 1.3341x; 1.2279x over previous
#include <cuda_runtime.h>
#include <math.h>
#include <stdint.h>

// ---------------------------------------------------------------------------
// Problem dims (fixed by the reference)
// ---------------------------------------------------------------------------
#define SEQ    2048
#define BATCH  32
#define DIM    1024
#define M_TOT  (SEQ * BATCH)     // 65536
#define N_TOT  (3 * DIM)         // 3072
#define K_TOT  DIM               // 1024

// GEMM tile
#define BM 128
#define BN 256
#define BK 32
#define NCHUNK (K_TOT / BK)      // 32
#define NSTAGE 3
#define ASTRIDE 36               // floats per SMEM row (32 + 4 pad): LDS banks
                                 // (36q + r)%32 = (4q+r)%32 all-distinct

// SMEM layout (bytes)
#define A_STG_BYTES (BM * ASTRIDE * 4)          // 18432
#define B_STG_BYTES (BN * ASTRIDE * 4)          // 36864
#define SMEM_B_BASE (NSTAGE * A_STG_BYTES)      // 55296
#define SMEM_BYTES  (SMEM_B_BASE + NSTAGE * B_STG_BYTES)  // 165888

// Scan chunking
#define NCHK    16
#define CHKLEN  (SEQ / NCHK)     // 128
#define NFCH    (BATCH * DIM / 4) // 8192 float4 chains

// Scratch (device globals; no cudaMalloc allowed)
__device__ float  g_act[(size_t)M_TOT * N_TOT];   // 768 MB activated gates
__device__ float  g_Xr[(size_t)M_TOT * K_TOT];    // 256 MB tf32-rounded X
__device__ float  g_Wr[(size_t)N_TOT * K_TOT];    // 12  MB tf32-rounded W
__device__ float4 g_A [(size_t)NCHK * NFCH];      // 2 MB per-chunk A = prod f
__device__ float4 g_B [(size_t)NCHK * NFCH];      // 2 MB per-chunk B
__device__ float4 g_h0[(size_t)NCHK * NFCH];      // 2 MB chunk entry states

// ---------------------------------------------------------------------------
// Helpers
// ---------------------------------------------------------------------------
__device__ __forceinline__ uint32_t smem_u32(const void* p) {
    uint32_t a;
    asm("{ .reg .u64 t; cvta.to.shared.u64 t, %1; cvt.u32.u64 %0, t; }"
        : "=r"(a) : "l"(p));
    return a;
}
__device__ __forceinline__ uint32_t tf32_rna(float x) {
    uint32_t r; asm("cvt.rna.tf32.f32 %0, %1;" : "=r"(r) : "f"(x)); return r;
}
__device__ __forceinline__ float rcp_fast(float x) {
    float r; asm("rcp.approx.f32 %0, %1;" : "=f"(r) : "f"(x)); return r;
}
__device__ __forceinline__ float sigmoid_f(float x) {
    return rcp_fast(1.0f + __expf(-x));
}
__device__ __forceinline__ float tanh_f(float x) {
    return 1.0f - 2.0f * rcp_fast(1.0f + __expf(2.0f * x));
}

__device__ __forceinline__ void cp_async16(uint32_t dst_smem, const void* src) {
    asm volatile("cp.async.cg.shared.global [%0], [%1], 16;"
                 :: "r"(dst_smem), "l"(src) : "memory");
}
__device__ __forceinline__ void cp_commit() {
    asm volatile("cp.async.commit_group;" ::: "memory");
}
template <int N>
__device__ __forceinline__ void cp_wait() {
    asm volatile("cp.async.wait_group %0;" :: "n"(N) : "memory");
}

// m16n8k8 tf32 HMMA (portable PTX, legal at compute_103)
__device__ __forceinline__ void mma_tf32(float* d,
                                         const uint32_t* a,
                                         const uint32_t* bb) {
    asm volatile(
        "mma.sync.aligned.m16n8k8.row.col.f32.tf32.tf32.f32 "
        "{%0,%1,%2,%3}, {%4,%5,%6,%7}, {%8,%9}, {%0,%1,%2,%3};\n"
        : "+f"(d[0]), "+f"(d[1]), "+f"(d[2]), "+f"(d[3])
        : "r"(a[0]), "r"(a[1]), "r"(a[2]), "r"(a[3]),
          "r"(bb[0]), "r"(bb[1]));
}

// ---------------------------------------------------------------------------
// Kernel 0: round fp32 -> tf32 (rna)
// ---------------------------------------------------------------------------
__global__ __launch_bounds__(256)
void round_tf32_kernel(const float* __restrict__ in, float* __restrict__ out, int n4)
{
    int i = blockIdx.x * blockDim.x + threadIdx.x;
    if (i >= n4) return;
    float4 v = ((const float4*)in)[i];
    float4 o;
    o.x = __uint_as_float(tf32_rna(v.x));
    o.y = __uint_as_float(tf32_rna(v.y));
    o.z = __uint_as_float(tf32_rna(v.z));
    o.w = __uint_as_float(tf32_rna(v.w));
    ((float4*)out)[i] = o;
}

// ---------------------------------------------------------------------------
// Kernel 1: cp.async 3-stage pipelined tf32 HMMA GEMM (R4 mainloop, known-good)
// ---------------------------------------------------------------------------
__global__ __launch_bounds__(256, 1)
void gemm_hmma_kernel(const float* __restrict__ b)
{
    extern __shared__ __align__(16) char smem[];
    const uint32_t sbase = smem_u32(smem);

    const int tid = threadIdx.x;
    const int wid = tid >> 5;
    const int lid = tid & 31;
    const int lq  = lid >> 2;
    const int lr  = lid & 3;

    const int wm = (wid >> 2) * 64;
    const int wn = (wid & 3) * 64;

    const int block_m = blockIdx.y * BM;
    const int block_n = blockIdx.x * BN;

    const float* Abase = g_Xr + (size_t)block_m * K_TOT;
    const float* Bbase = g_Wr + (size_t)block_n * K_TOT;

    float acc[4][8][4];
#pragma unroll
    for (int mt = 0; mt < 4; ++mt)
#pragma unroll
        for (int nt = 0; nt < 8; ++nt)
#pragma unroll
            for (int r = 0; r < 4; ++r) acc[mt][nt][r] = 0.0f;

#pragma unroll
    for (int p = 0; p < NSTAGE; ++p) {
        const int kcol = p * BK;
        const uint32_t a_s = sbase + p * A_STG_BYTES;
        const uint32_t b_s = sbase + SMEM_B_BASE + p * B_STG_BYTES;
#pragma unroll
        for (int i = 0; i < 4; ++i) {
            int pos = tid + i * 256;
            int r = pos >> 3, c4 = pos & 7;
            cp_async16(a_s + (uint32_t)(r * ASTRIDE + c4 * 4) * 4,
                       Abase + (size_t)r * K_TOT + kcol + c4 * 4);
        }
#pragma unroll
        for (int i = 0; i < 8; ++i) {
            int pos = tid + i * 256;
            int r = pos >> 3, c4 = pos & 7;
            cp_async16(b_s + (uint32_t)(r * ASTRIDE + c4 * 4) * 4,
                       Bbase + (size_t)r * K_TOT + kcol + c4 * 4);
        }
        cp_commit();
    }

    for (int c = 0; c < NCHUNK; ++c) {
        const int buf = c % NSTAGE;
        cp_wait<NSTAGE - 1>();
        __syncthreads();

        const uint32_t* As = (const uint32_t*)(smem + buf * A_STG_BYTES);
        const uint32_t* Bs = (const uint32_t*)(smem + SMEM_B_BASE + buf * B_STG_BYTES);

#pragma unroll
        for (int ks = 0; ks < 4; ++ks) {
            const int k0 = ks * 8;
            uint32_t afrag[4][4], bfrag[8][2];
#pragma unroll
            for (int mt = 0; mt < 4; ++mt) {
                int base = (wm + mt * 16 + lq) * ASTRIDE + k0 + lr;
                afrag[mt][0] = As[base];
                afrag[mt][1] = As[base + 8 * ASTRIDE];
                afrag[mt][2] = As[base + 4];
                afrag[mt][3] = As[base + 8 * ASTRIDE + 4];
            }
#pragma unroll
            for (int nt = 0; nt < 8; ++nt) {
                int base = (wn + nt * 8 + lq) * ASTRIDE + k0 + lr;
                bfrag[nt][0] = Bs[base];
                bfrag[nt][1] = Bs[base + 4];
            }
#pragma unroll
            for (int mt = 0; mt < 4; ++mt)
#pragma unroll
                for (int nt = 0; nt < 8; ++nt)
                    mma_tf32(acc[mt][nt], afrag[mt], bfrag[nt]);
        }

        __syncthreads();

        if (c + NSTAGE < NCHUNK) {
            const int kcol = (c + NSTAGE) * BK;
            const uint32_t a_s = sbase + buf * A_STG_BYTES;
            const uint32_t b_s = sbase + SMEM_B_BASE + buf * B_STG_BYTES;
#pragma unroll
            for (int i = 0; i < 4; ++i) {
                int pos = tid + i * 256;
                int r = pos >> 3, c4 = pos & 7;
                cp_async16(a_s + (uint32_t)(r * ASTRIDE + c4 * 4) * 4,
                           Abase + (size_t)r * K_TOT + kcol + c4 * 4);
            }
#pragma unroll
            for (int i = 0; i < 8; ++i) {
                int pos = tid + i * 256;
                int r = pos >> 3, c4 = pos & 7;
                cp_async16(b_s + (uint32_t)(r * ASTRIDE + c4 * 4) * 4,
                           Bbase + (size_t)r * K_TOT + kcol + c4 * 4);
            }
        }
        cp_commit();
    }

    const bool is_tanh = (block_n < DIM);

#pragma unroll
    for (int nt = 0; nt < 8; ++nt) {
        const int gc = block_n + wn + nt * 8 + 2 * lr;
        const float b0 = __ldg(&b[gc]);
        const float b1 = __ldg(&b[gc + 1]);
#pragma unroll
        for (int mt = 0; mt < 4; ++mt) {
            const int gm0 = block_m + wm + mt * 16 + lq;
            const int gm1 = gm0 + 8;
            float v00 = acc[mt][nt][0] + b0;
            float v01 = acc[mt][nt][1] + b1;
            float v10 = acc[mt][nt][2] + b0;
            float v11 = acc[mt][nt][3] + b1;
            float2 r0, r1;
            if (is_tanh) {
                r0.x = tanh_f(v00); r0.y = tanh_f(v01);
                r1.x = tanh_f(v10); r1.y = tanh_f(v11);
            } else {
                r0.x = sigmoid_f(v00); r0.y = sigmoid_f(v01);
                r1.x = sigmoid_f(v10); r1.y = sigmoid_f(v11);
            }
            *(float2*)(&g_act[(size_t)gm0 * N_TOT + gc]) = r0;
            *(float2*)(&g_act[(size_t)gm1 * N_TOT + gc]) = r1;
        }
    }
}

// ---------------------------------------------------------------------------
// Scan pass 1: per (chunk, float4-chain) compute affine map (A, B) of the
// chunk: h_out = A*h_in + B.  A = prod f, B = recurrence with h0 = 0.
// 131072 threads -> bandwidth-bound.
// ---------------------------------------------------------------------------
__global__ __launch_bounds__(128)
void scan_part1(void)
{
    const int g   = blockIdx.x * 128 + threadIdx.x;   // 0 .. NCHK*NFCH-1
    const int chk = g >> 13;                          // /8192
    const int fc  = g & (NFCH - 1);                   // chain-vec index
    const int bb  = fc >> 8;                          // batch
    const int dv  = fc & 255;                         // float4 within DIM

    const float4* __restrict__ act4 = (const float4*)g_act;

    float4 A = make_float4(1.f, 1.f, 1.f, 1.f);
    float4 B = make_float4(0.f, 0.f, 0.f, 0.f);

    const int s0 = chk * CHKLEN;
#pragma unroll 4
    for (int s = s0; s < s0 + CHKLEN; ++s) {
        const size_t row4 = (size_t)(s * BATCH + bb) * (N_TOT / 4);
        const float4 z = act4[row4 + dv];
        const float4 f = act4[row4 + 256 + dv];
        A.x *= f.x; A.y *= f.y; A.z *= f.z; A.w *= f.w;
        B.x = fmaf(f.x, B.x - z.x, z.x);
        B.y = fmaf(f.y, B.y - z.y, z.y);
        B.z = fmaf(f.z, B.z - z.z, z.z);
        B.w = fmaf(f.w, B.w - z.w, z.w);
    }
    g_A[(size_t)chk * NFCH + fc] = A;
    g_B[(size_t)chk * NFCH + fc] = B;
}

// ---------------------------------------------------------------------------
// Scan pass 2: compose chunk maps sequentially to get entry state h0 of each
// chunk.  8192 threads, ~8 MB traffic — negligible.
// ---------------------------------------------------------------------------
__global__ __launch_bounds__(128)
void scan_part2(const float* __restrict__ hidden)
{
    const int fc = blockIdx.x * 128 + threadIdx.x;    // 0..8191
    float4 h = ((const float4*)hidden)[fc];

#pragma unroll
    for (int c = 0; c < NCHK; ++c) {
        g_h0[(size_t)c * NFCH + fc] = h;
        const float4 A = g_A[(size_t)c * NFCH + fc];
        const float4 B = g_B[(size_t)c * NFCH + fc];
        h.x = fmaf(A.x, h.x, B.x);
        h.y = fmaf(A.y, h.y, B.y);
        h.z = fmaf(A.z, h.z, B.z);
        h.w = fmaf(A.w, h.w, B.w);
    }
}

// ---------------------------------------------------------------------------
// Scan pass 3: re-run the recurrence inside each chunk from its entry state,
// write H = o*h; chunk NCHK-1 writes h_n.  131072 threads.
// ---------------------------------------------------------------------------
__global__ __launch_bounds__(128)
void scan_part3(float* __restrict__ out)
{
    const int g   = blockIdx.x * 128 + threadIdx.x;
    const int chk = g >> 13;
    const int fc  = g & (NFCH - 1);
    const int bb  = fc >> 8;
    const int dv  = fc & 255;

    const float4* __restrict__ act4 = (const float4*)g_act;
    float4* __restrict__ H4  = (float4*)out;
    float4* __restrict__ hn4 = (float4*)(out + (size_t)SEQ * BATCH * DIM);

    float4 h = g_h0[(size_t)chk * NFCH + fc];

    const int s0 = chk * CHKLEN;
#pragma unroll 4
    for (int s = s0; s < s0 + CHKLEN; ++s) {
        const size_t row4 = (size_t)(s * BATCH + bb) * (N_TOT / 4);
        const float4 z = act4[row4 + dv];
        const float4 f = act4[row4 + 256 + dv];
        const float4 o = act4[row4 + 512 + dv];
        h.x = fmaf(f.x, h.x - z.x, z.x);
        h.y = fmaf(f.y, h.y - z.y, z.y);
        h.z = fmaf(f.z, h.z - z.z, z.z);
        h.w = fmaf(f.w, h.w - z.w, z.w);
        float4 r;
        r.x = o.x * h.x; r.y = o.y * h.y; r.z = o.z * h.z; r.w = o.w * h.w;
        H4[(size_t)(s * BATCH + bb) * 256 + dv] = r;
    }
    if (chk == NCHK - 1)
        hn4[fc] = h;
}

// ---------------------------------------------------------------------------
extern "C" void kernel_launch(void* const* d_in, const int* in_sizes, int n_in,
                              void* d_out, int out_size)
{
    const float* X      = (const float*)d_in[0];   // [2048, 32, 1024]
    const float* hidden = (const float*)d_in[1];   // [1, 32, 1024]
    const float* W      = (const float*)d_in[2];   // [3072, 1024]
    const float* b      = (const float*)d_in[3];   // [3072]
    float* out = (float*)d_out;

    cudaFuncSetAttribute(gemm_hmma_kernel,
                         cudaFuncAttributeMaxDynamicSharedMemorySize,
                         SMEM_BYTES);

    float* Xr; float* Wr;
    cudaGetSymbolAddress((void**)&Xr, g_Xr);
    cudaGetSymbolAddress((void**)&Wr, g_Wr);

    // round inputs to tf32 (rna)
    {
        int n4x = (M_TOT * K_TOT) / 4;
        round_tf32_kernel<<<n4x / 256, 256>>>(X, Xr, n4x);
        int n4w = (N_TOT * K_TOT) / 4;
        round_tf32_kernel<<<n4w / 256, 256>>>(W, Wr, n4w);
    }

    dim3 grid(N_TOT / BN, M_TOT / BM);   // (12, 512)
    gemm_hmma_kernel<<<grid, 256, SMEM_BYTES>>>(b);

    scan_part1<<<(NCHK * NFCH) / 128, 128>>>();
    scan_part2<<<NFCH / 128, 128>>>(hidden);
    scan_part3<<<(NCHK * NFCH) / 128, 128>>>(out);
}

// round 9
// speedup vs baseline: 1.3795x; 1.0340x over previous
#include <cuda_runtime.h>
#include <math.h>
#include <stdint.h>

// ---------------------------------------------------------------------------
// Problem dims (fixed by the reference)
// ---------------------------------------------------------------------------
#define SEQ    2048
#define BATCH  32
#define DIM    1024
#define M_TOT  (SEQ * BATCH)     // 65536
#define N_TOT  (3 * DIM)         // 3072
#define K_TOT  DIM               // 1024

// GEMM tile (2 CTAs/SM config)
#define BM 128
#define BN 128
#define BK 32
#define NCHUNK (K_TOT / BK)      // 32
#define NSTAGE 3
#define ASTRIDE 36               // floats per SMEM row (32 + 4 pad): LDS banks
                                 // (36q + r)%32 = (4q+r)%32 all-distinct

// SMEM layout (bytes)
#define A_STG_BYTES (BM * ASTRIDE * 4)          // 18432
#define B_STG_BYTES (BN * ASTRIDE * 4)          // 18432
#define SMEM_B_BASE (NSTAGE * A_STG_BYTES)      // 55296
#define SMEM_BYTES  (SMEM_B_BASE + NSTAGE * B_STG_BYTES)  // 110592

// Scan chunking
#define NCHK    16
#define CHKLEN  (SEQ / NCHK)      // 128
#define NFCH    (BATCH * DIM / 4) // 8192 float4 chains

// Scratch (device globals; no cudaMalloc allowed)
__device__ float  g_act[(size_t)M_TOT * N_TOT];   // 768 MB activated gates
__device__ float  g_Xr[(size_t)M_TOT * K_TOT];    // 256 MB tf32-rounded X
__device__ float  g_Wr[(size_t)N_TOT * K_TOT];    // 12  MB tf32-rounded W
__device__ float4 g_A [(size_t)NCHK * NFCH];      // per-chunk A = prod f
__device__ float4 g_B [(size_t)NCHK * NFCH];      // per-chunk B
__device__ float4 g_h0[(size_t)NCHK * NFCH];      // chunk entry states

// ---------------------------------------------------------------------------
// Helpers
// ---------------------------------------------------------------------------
__device__ __forceinline__ uint32_t smem_u32(const void* p) {
    uint32_t a;
    asm("{ .reg .u64 t; cvta.to.shared.u64 t, %1; cvt.u32.u64 %0, t; }"
        : "=r"(a) : "l"(p));
    return a;
}
__device__ __forceinline__ uint32_t tf32_rna(float x) {
    uint32_t r; asm("cvt.rna.tf32.f32 %0, %1;" : "=r"(r) : "f"(x)); return r;
}
__device__ __forceinline__ float rcp_fast(float x) {
    float r; asm("rcp.approx.f32 %0, %1;" : "=f"(r) : "f"(x)); return r;
}
__device__ __forceinline__ float sigmoid_f(float x) {
    return rcp_fast(1.0f + __expf(-x));
}
__device__ __forceinline__ float tanh_f(float x) {
    return 1.0f - 2.0f * rcp_fast(1.0f + __expf(2.0f * x));
}

__device__ __forceinline__ void cp_async16(uint32_t dst_smem, const void* src) {
    asm volatile("cp.async.cg.shared.global [%0], [%1], 16;"
                 :: "r"(dst_smem), "l"(src) : "memory");
}
__device__ __forceinline__ void cp_commit() {
    asm volatile("cp.async.commit_group;" ::: "memory");
}
template <int N>
__device__ __forceinline__ void cp_wait() {
    asm volatile("cp.async.wait_group %0;" :: "n"(N) : "memory");
}

// m16n8k8 tf32 HMMA (portable PTX, legal at compute_103)
__device__ __forceinline__ void mma_tf32(float* d,
                                         const uint32_t* a,
                                         const uint32_t* bb) {
    asm volatile(
        "mma.sync.aligned.m16n8k8.row.col.f32.tf32.tf32.f32 "
        "{%0,%1,%2,%3}, {%4,%5,%6,%7}, {%8,%9}, {%0,%1,%2,%3};\n"
        : "+f"(d[0]), "+f"(d[1]), "+f"(d[2]), "+f"(d[3])
        : "r"(a[0]), "r"(a[1]), "r"(a[2]), "r"(a[3]),
          "r"(bb[0]), "r"(bb[1]));
}

// ---------------------------------------------------------------------------
// Kernel 0: round fp32 -> tf32 (rna)
// ---------------------------------------------------------------------------
__global__ __launch_bounds__(256)
void round_tf32_kernel(const float* __restrict__ in, float* __restrict__ out, int n4)
{
    int i = blockIdx.x * blockDim.x + threadIdx.x;
    if (i >= n4) return;
    float4 v = ((const float4*)in)[i];
    float4 o;
    o.x = __uint_as_float(tf32_rna(v.x));
    o.y = __uint_as_float(tf32_rna(v.y));
    o.z = __uint_as_float(tf32_rna(v.z));
    o.w = __uint_as_float(tf32_rna(v.w));
    ((float4*)out)[i] = o;
}

// ---------------------------------------------------------------------------
// Kernel 1: cp.async 3-stage pipelined tf32 HMMA GEMM, 2 CTAs/SM.
//   C = Xr @ Wr^T + b, fused activation -> g_act
//   256 threads = 8 warps in 2(M) x 4(N); warp tile 64x32 (4x4 m16n8k8 grid)
//   BN=128, SMEM 110.6 KB -> two CTAs co-resident; one CTA's MMA phase
//   overlaps the other's LDS/sync phase.
// ---------------------------------------------------------------------------
__global__ __launch_bounds__(256, 2)
void gemm_hmma_kernel(const float* __restrict__ b)
{
    extern __shared__ __align__(16) char smem[];
    const uint32_t sbase = smem_u32(smem);

    const int tid = threadIdx.x;
    const int wid = tid >> 5;
    const int lid = tid & 31;
    const int lq  = lid >> 2;   // 0..7
    const int lr  = lid & 3;    // 0..3

    const int wm = (wid >> 2) * 64;   // warp M offset: 0 / 64
    const int wn = (wid & 3) * 32;    // warp N offset: 0..96

    const int block_m = blockIdx.y * BM;
    const int block_n = blockIdx.x * BN;

    const float* Abase = g_Xr + (size_t)block_m * K_TOT;
    const float* Bbase = g_Wr + (size_t)block_n * K_TOT;

    float acc[4][4][4];
#pragma unroll
    for (int mt = 0; mt < 4; ++mt)
#pragma unroll
        for (int nt = 0; nt < 4; ++nt)
#pragma unroll
            for (int r = 0; r < 4; ++r) acc[mt][nt][r] = 0.0f;

    // staging: A chunk = 128 rows x 8 float4 = 1024 float4 (4/thread); B same.
#pragma unroll
    for (int p = 0; p < NSTAGE; ++p) {
        const int kcol = p * BK;
        const uint32_t a_s = sbase + p * A_STG_BYTES;
        const uint32_t b_s = sbase + SMEM_B_BASE + p * B_STG_BYTES;
#pragma unroll
        for (int i = 0; i < 4; ++i) {
            int pos = tid + i * 256;
            int r = pos >> 3, c4 = pos & 7;
            cp_async16(a_s + (uint32_t)(r * ASTRIDE + c4 * 4) * 4,
                       Abase + (size_t)r * K_TOT + kcol + c4 * 4);
        }
#pragma unroll
        for (int i = 0; i < 4; ++i) {
            int pos = tid + i * 256;
            int r = pos >> 3, c4 = pos & 7;
            cp_async16(b_s + (uint32_t)(r * ASTRIDE + c4 * 4) * 4,
                       Bbase + (size_t)r * K_TOT + kcol + c4 * 4);
        }
        cp_commit();
    }

    for (int c = 0; c < NCHUNK; ++c) {
        const int buf = c % NSTAGE;
        cp_wait<NSTAGE - 1>();
        __syncthreads();

        const uint32_t* As = (const uint32_t*)(smem + buf * A_STG_BYTES);
        const uint32_t* Bs = (const uint32_t*)(smem + SMEM_B_BASE + buf * B_STG_BYTES);

#pragma unroll
        for (int ks = 0; ks < 4; ++ks) {
            const int k0 = ks * 8;
            uint32_t afrag[4][4], bfrag[4][2];
#pragma unroll
            for (int mt = 0; mt < 4; ++mt) {
                int base = (wm + mt * 16 + lq) * ASTRIDE + k0 + lr;
                afrag[mt][0] = As[base];
                afrag[mt][1] = As[base + 8 * ASTRIDE];
                afrag[mt][2] = As[base + 4];
                afrag[mt][3] = As[base + 8 * ASTRIDE + 4];
            }
#pragma unroll
            for (int nt = 0; nt < 4; ++nt) {
                int base = (wn + nt * 8 + lq) * ASTRIDE + k0 + lr;
                bfrag[nt][0] = Bs[base];
                bfrag[nt][1] = Bs[base + 4];
            }
#pragma unroll
            for (int mt = 0; mt < 4; ++mt)
#pragma unroll
                for (int nt = 0; nt < 4; ++nt)
                    mma_tf32(acc[mt][nt], afrag[mt], bfrag[nt]);
        }

        __syncthreads();   // all warps done reading buf before refill

        if (c + NSTAGE < NCHUNK) {
            const int kcol = (c + NSTAGE) * BK;
            const uint32_t a_s = sbase + buf * A_STG_BYTES;
            const uint32_t b_s = sbase + SMEM_B_BASE + buf * B_STG_BYTES;
#pragma unroll
            for (int i = 0; i < 4; ++i) {
                int pos = tid + i * 256;
                int r = pos >> 3, c4 = pos & 7;
                cp_async16(a_s + (uint32_t)(r * ASTRIDE + c4 * 4) * 4,
                           Abase + (size_t)r * K_TOT + kcol + c4 * 4);
            }
#pragma unroll
            for (int i = 0; i < 4; ++i) {
                int pos = tid + i * 256;
                int r = pos >> 3, c4 = pos & 7;
                cp_async16(b_s + (uint32_t)(r * ASTRIDE + c4 * 4) * 4,
                           Bbase + (size_t)r * K_TOT + kcol + c4 * 4);
            }
        }
        cp_commit();   // keep group accounting uniform
    }

    // ---- epilogue: bias + activation -> g_act ----
    const bool is_tanh = (block_n < DIM);   // BN=128 divides DIM

#pragma unroll
    for (int nt = 0; nt < 4; ++nt) {
        const int gc = block_n + wn + nt * 8 + 2 * lr;
        const float b0 = __ldg(&b[gc]);
        const float b1 = __ldg(&b[gc + 1]);
#pragma unroll
        for (int mt = 0; mt < 4; ++mt) {
            const int gm0 = block_m + wm + mt * 16 + lq;
            const int gm1 = gm0 + 8;
            float v00 = acc[mt][nt][0] + b0;
            float v01 = acc[mt][nt][1] + b1;
            float v10 = acc[mt][nt][2] + b0;
            float v11 = acc[mt][nt][3] + b1;
            float2 r0, r1;
            if (is_tanh) {
                r0.x = tanh_f(v00); r0.y = tanh_f(v01);
                r1.x = tanh_f(v10); r1.y = tanh_f(v11);
            } else {
                r0.x = sigmoid_f(v00); r0.y = sigmoid_f(v01);
                r1.x = sigmoid_f(v10); r1.y = sigmoid_f(v11);
            }
            *(float2*)(&g_act[(size_t)gm0 * N_TOT + gc]) = r0;
            *(float2*)(&g_act[(size_t)gm1 * N_TOT + gc]) = r1;
        }
    }
}

// ---------------------------------------------------------------------------
// Scan pass 1: per (chunk, float4-chain) affine map (A, B): h_out = A*h_in + B
// ---------------------------------------------------------------------------
__global__ __launch_bounds__(128)
void scan_part1(void)
{
    const int g   = blockIdx.x * 128 + threadIdx.x;   // 0 .. NCHK*NFCH-1
    const int chk = g >> 13;
    const int fc  = g & (NFCH - 1);
    const int bb  = fc >> 8;
    const int dv  = fc & 255;

    const float4* __restrict__ act4 = (const float4*)g_act;

    float4 A = make_float4(1.f, 1.f, 1.f, 1.f);
    float4 B = make_float4(0.f, 0.f, 0.f, 0.f);

    const int s0 = chk * CHKLEN;
#pragma unroll 4
    for (int s = s0; s < s0 + CHKLEN; ++s) {
        const size_t row4 = (size_t)(s * BATCH + bb) * (N_TOT / 4);
        const float4 z = act4[row4 + dv];
        const float4 f = act4[row4 + 256 + dv];
        A.x *= f.x; A.y *= f.y; A.z *= f.z; A.w *= f.w;
        B.x = fmaf(f.x, B.x - z.x, z.x);
        B.y = fmaf(f.y, B.y - z.y, z.y);
        B.z = fmaf(f.z, B.z - z.z, z.z);
        B.w = fmaf(f.w, B.w - z.w, z.w);
    }
    g_A[(size_t)chk * NFCH + fc] = A;
    g_B[(size_t)chk * NFCH + fc] = B;
}

// ---------------------------------------------------------------------------
// Scan pass 2: compose chunk maps sequentially -> entry state h0 per chunk
// ---------------------------------------------------------------------------
__global__ __launch_bounds__(128)
void scan_part2(const float* __restrict__ hidden)
{
    const int fc = blockIdx.x * 128 + threadIdx.x;    // 0..8191
    float4 h = ((const float4*)hidden)[fc];

#pragma unroll
    for (int c = 0; c < NCHK; ++c) {
        g_h0[(size_t)c * NFCH + fc] = h;
        const float4 A = g_A[(size_t)c * NFCH + fc];
        const float4 B = g_B[(size_t)c * NFCH + fc];
        h.x = fmaf(A.x, h.x, B.x);
        h.y = fmaf(A.y, h.y, B.y);
        h.z = fmaf(A.z, h.z, B.z);
        h.w = fmaf(A.w, h.w, B.w);
    }
}

// ---------------------------------------------------------------------------
// Scan pass 3: rerun recurrence per chunk from h0, write H = o*h (+ h_n)
// ---------------------------------------------------------------------------
__global__ __launch_bounds__(128)
void scan_part3(float* __restrict__ out)
{
    const int g   = blockIdx.x * 128 + threadIdx.x;
    const int chk = g >> 13;
    const int fc  = g & (NFCH - 1);
    const int bb  = fc >> 8;
    const int dv  = fc & 255;

    const float4* __restrict__ act4 = (const float4*)g_act;
    float4* __restrict__ H4  = (float4*)out;
    float4* __restrict__ hn4 = (float4*)(out + (size_t)SEQ * BATCH * DIM);

    float4 h = g_h0[(size_t)chk * NFCH + fc];

    const int s0 = chk * CHKLEN;
#pragma unroll 4
    for (int s = s0; s < s0 + CHKLEN; ++s) {
        const size_t row4 = (size_t)(s * BATCH + bb) * (N_TOT / 4);
        const float4 z = act4[row4 + dv];
        const float4 f = act4[row4 + 256 + dv];
        const float4 o = act4[row4 + 512 + dv];
        h.x = fmaf(f.x, h.x - z.x, z.x);
        h.y = fmaf(f.y, h.y - z.y, z.y);
        h.z = fmaf(f.z, h.z - z.z, z.z);
        h.w = fmaf(f.w, h.w - z.w, z.w);
        float4 r;
        r.x = o.x * h.x; r.y = o.y * h.y; r.z = o.z * h.z; r.w = o.w * h.w;
        H4[(size_t)(s * BATCH + bb) * 256 + dv] = r;
    }
    if (chk == NCHK - 1)
        hn4[fc] = h;
}

// ---------------------------------------------------------------------------
extern "C" void kernel_launch(void* const* d_in, const int* in_sizes, int n_in,
                              void* d_out, int out_size)
{
    const float* X      = (const float*)d_in[0];   // [2048, 32, 1024]
    const float* hidden = (const float*)d_in[1];   // [1, 32, 1024]
    const float* W      = (const float*)d_in[2];   // [3072, 1024]
    const float* b      = (const float*)d_in[3];   // [3072]
    float* out = (float*)d_out;

    cudaFuncSetAttribute(gemm_hmma_kernel,
                         cudaFuncAttributeMaxDynamicSharedMemorySize,
                         SMEM_BYTES);

    float* Xr; float* Wr;
    cudaGetSymbolAddress((void**)&Xr, g_Xr);
    cudaGetSymbolAddress((void**)&Wr, g_Wr);

    // round inputs to tf32 (rna)
    {
        int n4x = (M_TOT * K_TOT) / 4;
        round_tf32_kernel<<<n4x / 256, 256>>>(X, Xr, n4x);
        int n4w = (N_TOT * K_TOT) / 4;
        round_tf32_kernel<<<n4w / 256, 256>>>(W, Wr, n4w);
    }

    dim3 grid(N_TOT / BN, M_TOT / BM);   // (24, 512)
    gemm_hmma_kernel<<<grid, 256, SMEM_BYTES>>>(b);

    scan_part1<<<(NCHK * NFCH) / 128, 128>>>();
    scan_part2<<<NFCH / 128, 128>>>(hidden);
    scan_part3<<<(NCHK * NFCH) / 128, 128>>>(out);
}

// round 10
// speedup vs baseline: 1.3988x; 1.0140x over previous
#include <cuda_runtime.h>
#include <math.h>
#include <stdint.h>

// ---------------------------------------------------------------------------
// Problem dims (fixed by the reference)
// ---------------------------------------------------------------------------
#define SEQ    2048
#define BATCH  32
#define DIM    1024
#define M_TOT  (SEQ * BATCH)     // 65536
#define N_TOT  (3 * DIM)         // 3072
#define K_TOT  DIM               // 1024

// GEMM tile: 128-thread CTAs (4 warps, 64x64 warp tiles), 2 CTAs/SM
#define BM 128
#define BN 128
#define BK 32
#define NCHUNK (K_TOT / BK)      // 32
#define NSTAGE 3
#define ASTRIDE 36               // floats per SMEM row (32 + 4 pad): LDS banks
                                 // (36q + r)%32 = (4q+r)%32 all-distinct

// SMEM layout (bytes)
#define A_STG_BYTES (BM * ASTRIDE * 4)          // 18432
#define B_STG_BYTES (BN * ASTRIDE * 4)          // 18432
#define SMEM_B_BASE (NSTAGE * A_STG_BYTES)      // 55296
#define SMEM_BYTES  (SMEM_B_BASE + NSTAGE * B_STG_BYTES)  // 110592

// Scan chunking
#define NCHK    16
#define CHKLEN  (SEQ / NCHK)      // 128
#define NFCH    (BATCH * DIM / 4) // 8192 float4 chains

// Scratch (device globals; no cudaMalloc allowed)
__device__ float  g_act[(size_t)M_TOT * N_TOT];   // 768 MB activated gates
__device__ float  g_Xr[(size_t)M_TOT * K_TOT];    // 256 MB tf32-rounded X
__device__ float  g_Wr[(size_t)N_TOT * K_TOT];    // 12  MB tf32-rounded W
__device__ float4 g_A [(size_t)NCHK * NFCH];      // per-chunk A = prod f
__device__ float4 g_B [(size_t)NCHK * NFCH];      // per-chunk B
__device__ float4 g_h0[(size_t)NCHK * NFCH];      // chunk entry states

// ---------------------------------------------------------------------------
// Helpers
// ---------------------------------------------------------------------------
__device__ __forceinline__ uint32_t smem_u32(const void* p) {
    uint32_t a;
    asm("{ .reg .u64 t; cvta.to.shared.u64 t, %1; cvt.u32.u64 %0, t; }"
        : "=r"(a) : "l"(p));
    return a;
}
__device__ __forceinline__ uint32_t tf32_rna(float x) {
    uint32_t r; asm("cvt.rna.tf32.f32 %0, %1;" : "=r"(r) : "f"(x)); return r;
}
__device__ __forceinline__ float rcp_fast(float x) {
    float r; asm("rcp.approx.f32 %0, %1;" : "=f"(r) : "f"(x)); return r;
}
__device__ __forceinline__ float sigmoid_f(float x) {
    return rcp_fast(1.0f + __expf(-x));
}
__device__ __forceinline__ float tanh_f(float x) {
    return 1.0f - 2.0f * rcp_fast(1.0f + __expf(2.0f * x));
}

__device__ __forceinline__ void cp_async16(uint32_t dst_smem, const void* src) {
    asm volatile("cp.async.cg.shared.global [%0], [%1], 16;"
                 :: "r"(dst_smem), "l"(src) : "memory");
}
__device__ __forceinline__ void cp_commit() {
    asm volatile("cp.async.commit_group;" ::: "memory");
}
template <int N>
__device__ __forceinline__ void cp_wait() {
    asm volatile("cp.async.wait_group %0;" :: "n"(N) : "memory");
}

// m16n8k8 tf32 HMMA (portable PTX, legal at compute_103)
__device__ __forceinline__ void mma_tf32(float* d,
                                         const uint32_t* a,
                                         const uint32_t* bb) {
    asm volatile(
        "mma.sync.aligned.m16n8k8.row.col.f32.tf32.tf32.f32 "
        "{%0,%1,%2,%3}, {%4,%5,%6,%7}, {%8,%9}, {%0,%1,%2,%3};\n"
        : "+f"(d[0]), "+f"(d[1]), "+f"(d[2]), "+f"(d[3])
        : "r"(a[0]), "r"(a[1]), "r"(a[2]), "r"(a[3]),
          "r"(bb[0]), "r"(bb[1]));
}

// ---------------------------------------------------------------------------
// Kernel 0: round fp32 -> tf32 (rna)
// ---------------------------------------------------------------------------
__global__ __launch_bounds__(256)
void round_tf32_kernel(const float* __restrict__ in, float* __restrict__ out, int n4)
{
    int i = blockIdx.x * blockDim.x + threadIdx.x;
    if (i >= n4) return;
    float4 v = ((const float4*)in)[i];
    float4 o;
    o.x = __uint_as_float(tf32_rna(v.x));
    o.y = __uint_as_float(tf32_rna(v.y));
    o.z = __uint_as_float(tf32_rna(v.z));
    o.w = __uint_as_float(tf32_rna(v.w));
    ((float4*)out)[i] = o;
}

// ---------------------------------------------------------------------------
// Kernel 1: cp.async 3-stage pipelined tf32 HMMA GEMM.
//   128 threads = 4 warps in 2(M) x 2(N); warp tile 64x64 (4x8 m16n8k8 grid)
//   -> LDS:MMA ratio 1.0, AND 2 CTAs/SM so phases overlap across CTAs.
// ---------------------------------------------------------------------------
__global__ __launch_bounds__(128, 2)
void gemm_hmma_kernel(const float* __restrict__ b)
{
    extern __shared__ __align__(16) char smem[];
    const uint32_t sbase = smem_u32(smem);

    const int tid = threadIdx.x;
    const int wid = tid >> 5;       // 0..3
    const int lid = tid & 31;
    const int lq  = lid >> 2;       // 0..7
    const int lr  = lid & 3;        // 0..3

    const int wm = (wid >> 1) * 64; // warp M offset: 0 / 64
    const int wn = (wid & 1) * 64;  // warp N offset: 0 / 64

    const int block_m = blockIdx.y * BM;
    const int block_n = blockIdx.x * BN;

    const float* Abase = g_Xr + (size_t)block_m * K_TOT;
    const float* Bbase = g_Wr + (size_t)block_n * K_TOT;

    float acc[4][8][4];
#pragma unroll
    for (int mt = 0; mt < 4; ++mt)
#pragma unroll
        for (int nt = 0; nt < 8; ++nt)
#pragma unroll
            for (int r = 0; r < 4; ++r) acc[mt][nt][r] = 0.0f;

    // staging: A chunk = 128 rows x 8 float4 = 1024 float4 (8/thread); B same.
#pragma unroll
    for (int p = 0; p < NSTAGE; ++p) {
        const int kcol = p * BK;
        const uint32_t a_s = sbase + p * A_STG_BYTES;
        const uint32_t b_s = sbase + SMEM_B_BASE + p * B_STG_BYTES;
#pragma unroll
        for (int i = 0; i < 8; ++i) {
            int pos = tid + i * 128;
            int r = pos >> 3, c4 = pos & 7;
            cp_async16(a_s + (uint32_t)(r * ASTRIDE + c4 * 4) * 4,
                       Abase + (size_t)r * K_TOT + kcol + c4 * 4);
        }
#pragma unroll
        for (int i = 0; i < 8; ++i) {
            int pos = tid + i * 128;
            int r = pos >> 3, c4 = pos & 7;
            cp_async16(b_s + (uint32_t)(r * ASTRIDE + c4 * 4) * 4,
                       Bbase + (size_t)r * K_TOT + kcol + c4 * 4);
        }
        cp_commit();
    }

    for (int c = 0; c < NCHUNK; ++c) {
        const int buf = c % NSTAGE;
        cp_wait<NSTAGE - 1>();
        __syncthreads();

        const uint32_t* As = (const uint32_t*)(smem + buf * A_STG_BYTES);
        const uint32_t* Bs = (const uint32_t*)(smem + SMEM_B_BASE + buf * B_STG_BYTES);

#pragma unroll
        for (int ks = 0; ks < 4; ++ks) {
            const int k0 = ks * 8;
            uint32_t afrag[4][4], bfrag[8][2];
#pragma unroll
            for (int mt = 0; mt < 4; ++mt) {
                int base = (wm + mt * 16 + lq) * ASTRIDE + k0 + lr;
                afrag[mt][0] = As[base];
                afrag[mt][1] = As[base + 8 * ASTRIDE];
                afrag[mt][2] = As[base + 4];
                afrag[mt][3] = As[base + 8 * ASTRIDE + 4];
            }
#pragma unroll
            for (int nt = 0; nt < 8; ++nt) {
                int base = (wn + nt * 8 + lq) * ASTRIDE + k0 + lr;
                bfrag[nt][0] = Bs[base];
                bfrag[nt][1] = Bs[base + 4];
            }
#pragma unroll
            for (int mt = 0; mt < 4; ++mt)
#pragma unroll
                for (int nt = 0; nt < 8; ++nt)
                    mma_tf32(acc[mt][nt], afrag[mt], bfrag[nt]);
        }

        __syncthreads();   // all warps done reading buf before refill

        if (c + NSTAGE < NCHUNK) {
            const int kcol = (c + NSTAGE) * BK;
            const uint32_t a_s = sbase + buf * A_STG_BYTES;
            const uint32_t b_s = sbase + SMEM_B_BASE + buf * B_STG_BYTES;
#pragma unroll
            for (int i = 0; i < 8; ++i) {
                int pos = tid + i * 128;
                int r = pos >> 3, c4 = pos & 7;
                cp_async16(a_s + (uint32_t)(r * ASTRIDE + c4 * 4) * 4,
                           Abase + (size_t)r * K_TOT + kcol + c4 * 4);
            }
#pragma unroll
            for (int i = 0; i < 8; ++i) {
                int pos = tid + i * 128;
                int r = pos >> 3, c4 = pos & 7;
                cp_async16(b_s + (uint32_t)(r * ASTRIDE + c4 * 4) * 4,
                           Bbase + (size_t)r * K_TOT + kcol + c4 * 4);
            }
        }
        cp_commit();   // keep group accounting uniform
    }

    // ---- epilogue: bias + activation -> g_act ----
    const bool is_tanh = (block_n < DIM);   // BN=128 divides DIM

#pragma unroll
    for (int nt = 0; nt < 8; ++nt) {
        const int gc = block_n + wn + nt * 8 + 2 * lr;
        const float b0 = __ldg(&b[gc]);
        const float b1 = __ldg(&b[gc + 1]);
#pragma unroll
        for (int mt = 0; mt < 4; ++mt) {
            const int gm0 = block_m + wm + mt * 16 + lq;
            const int gm1 = gm0 + 8;
            float v00 = acc[mt][nt][0] + b0;
            float v01 = acc[mt][nt][1] + b1;
            float v10 = acc[mt][nt][2] + b0;
            float v11 = acc[mt][nt][3] + b1;
            float2 r0, r1;
            if (is_tanh) {
                r0.x = tanh_f(v00); r0.y = tanh_f(v01);
                r1.x = tanh_f(v10); r1.y = tanh_f(v11);
            } else {
                r0.x = sigmoid_f(v00); r0.y = sigmoid_f(v01);
                r1.x = sigmoid_f(v10); r1.y = sigmoid_f(v11);
            }
            *(float2*)(&g_act[(size_t)gm0 * N_TOT + gc]) = r0;
            *(float2*)(&g_act[(size_t)gm1 * N_TOT + gc]) = r1;
        }
    }
}

// ---------------------------------------------------------------------------
// Scan pass 1: per (chunk, float4-chain) affine map (A, B): h_out = A*h_in + B
// ---------------------------------------------------------------------------
__global__ __launch_bounds__(128)
void scan_part1(void)
{
    const int g   = blockIdx.x * 128 + threadIdx.x;   // 0 .. NCHK*NFCH-1
    const int chk = g >> 13;
    const int fc  = g & (NFCH - 1);
    const int bb  = fc >> 8;
    const int dv  = fc & 255;

    const float4* __restrict__ act4 = (const float4*)g_act;

    float4 A = make_float4(1.f, 1.f, 1.f, 1.f);
    float4 B = make_float4(0.f, 0.f, 0.f, 0.f);

    const int s0 = chk * CHKLEN;
#pragma unroll 4
    for (int s = s0; s < s0 + CHKLEN; ++s) {
        const size_t row4 = (size_t)(s * BATCH + bb) * (N_TOT / 4);
        const float4 z = act4[row4 + dv];
        const float4 f = act4[row4 + 256 + dv];
        A.x *= f.x; A.y *= f.y; A.z *= f.z; A.w *= f.w;
        B.x = fmaf(f.x, B.x - z.x, z.x);
        B.y = fmaf(f.y, B.y - z.y, z.y);
        B.z = fmaf(f.z, B.z - z.z, z.z);
        B.w = fmaf(f.w, B.w - z.w, z.w);
    }
    g_A[(size_t)chk * NFCH + fc] = A;
    g_B[(size_t)chk * NFCH + fc] = B;
}

// ---------------------------------------------------------------------------
// Scan pass 2: compose chunk maps sequentially -> entry state h0 per chunk
// ---------------------------------------------------------------------------
__global__ __launch_bounds__(128)
void scan_part2(const float* __restrict__ hidden)
{
    const int fc = blockIdx.x * 128 + threadIdx.x;    // 0..8191
    float4 h = ((const float4*)hidden)[fc];

#pragma unroll
    for (int c = 0; c < NCHK; ++c) {
        g_h0[(size_t)c * NFCH + fc] = h;
        const float4 A = g_A[(size_t)c * NFCH + fc];
        const float4 B = g_B[(size_t)c * NFCH + fc];
        h.x = fmaf(A.x, h.x, B.x);
        h.y = fmaf(A.y, h.y, B.y);
        h.z = fmaf(A.z, h.z, B.z);
        h.w = fmaf(A.w, h.w, B.w);
    }
}

// ---------------------------------------------------------------------------
// Scan pass 3: rerun recurrence per chunk from h0, write H = o*h (+ h_n)
// ---------------------------------------------------------------------------
__global__ __launch_bounds__(128)
void scan_part3(float* __restrict__ out)
{
    const int g   = blockIdx.x * 128 + threadIdx.x;
    const int chk = g >> 13;
    const int fc  = g & (NFCH - 1);
    const int bb  = fc >> 8;
    const int dv  = fc & 255;

    const float4* __restrict__ act4 = (const float4*)g_act;
    float4* __restrict__ H4  = (float4*)out;
    float4* __restrict__ hn4 = (float4*)(out + (size_t)SEQ * BATCH * DIM);

    float4 h = g_h0[(size_t)chk * NFCH + fc];

    const int s0 = chk * CHKLEN;
#pragma unroll 4
    for (int s = s0; s < s0 + CHKLEN; ++s) {
        const size_t row4 = (size_t)(s * BATCH + bb) * (N_TOT / 4);
        const float4 z = act4[row4 + dv];
        const float4 f = act4[row4 + 256 + dv];
        const float4 o = act4[row4 + 512 + dv];
        h.x = fmaf(f.x, h.x - z.x, z.x);
        h.y = fmaf(f.y, h.y - z.y, z.y);
        h.z = fmaf(f.z, h.z - z.z, z.z);
        h.w = fmaf(f.w, h.w - z.w, z.w);
        float4 r;
        r.x = o.x * h.x; r.y = o.y * h.y; r.z = o.z * h.z; r.w = o.w * h.w;
        H4[(size_t)(s * BATCH + bb) * 256 + dv] = r;
    }
    if (chk == NCHK - 1)
        hn4[fc] = h;
}

// ---------------------------------------------------------------------------
extern "C" void kernel_launch(void* const* d_in, const int* in_sizes, int n_in,
                              void* d_out, int out_size)
{
    const float* X      = (const float*)d_in[0];   // [2048, 32, 1024]
    const float* hidden = (const float*)d_in[1];   // [1, 32, 1024]
    const float* W      = (const float*)d_in[2];   // [3072, 1024]
    const float* b      = (const float*)d_in[3];   // [3072]
    float* out = (float*)d_out;

    cudaFuncSetAttribute(gemm_hmma_kernel,
                         cudaFuncAttributeMaxDynamicSharedMemorySize,
                         SMEM_BYTES);

    float* Xr; float* Wr;
    cudaGetSymbolAddress((void**)&Xr, g_Xr);
    cudaGetSymbolAddress((void**)&Wr, g_Wr);

    // round inputs to tf32 (rna)
    {
        int n4x = (M_TOT * K_TOT) / 4;
        round_tf32_kernel<<<n4x / 256, 256>>>(X, Xr, n4x);
        int n4w = (N_TOT * K_TOT) / 4;
        round_tf32_kernel<<<n4w / 256, 256>>>(W, Wr, n4w);
    }

    dim3 grid(N_TOT / BN, M_TOT / BM);   // (24, 512)
    gemm_hmma_kernel<<<grid, 128, SMEM_BYTES>>>(b);

    scan_part1<<<(NCHK * NFCH) / 128, 128>>>();
    scan_part2<<<NFCH / 128, 128>>>(hidden);
    scan_part3<<<(NCHK * NFCH) / 128, 128>>>(out);
}

// round 11
// speedup vs baseline: 1.4222x; 1.0167x over previous
#include <cuda_runtime.h>
#include <cuda_fp16.h>
#include <math.h>
#include <stdint.h>

// ---------------------------------------------------------------------------
// Problem dims (fixed by the reference)
// ---------------------------------------------------------------------------
#define SEQ    2048
#define BATCH  32
#define DIM    1024
#define M_TOT  (SEQ * BATCH)     // 65536
#define N_TOT  (3 * DIM)         // 3072
#define K_TOT  DIM               // 1024

// GEMM tile: 128-thread CTAs (4 warps, 64x64 warp tiles), 2 CTAs/SM
#define BM 128
#define BN 128
#define BK 32
#define NCHUNK (K_TOT / BK)      // 32
#define NSTAGE 3
#define ASTRIDE 36               // floats per SMEM row (32 + 4 pad): LDS banks
                                 // (36q + r)%32 = (4q+r)%32 all-distinct

// SMEM layout (bytes)
#define A_STG_BYTES (BM * ASTRIDE * 4)          // 18432
#define B_STG_BYTES (BN * ASTRIDE * 4)          // 18432
#define SMEM_B_BASE (NSTAGE * A_STG_BYTES)      // 55296
#define SMEM_BYTES  (SMEM_B_BASE + NSTAGE * B_STG_BYTES)  // 110592

// Scan chunking: 8 features per thread (one uint4 = 8 fp16 per gate load)
#define NCHK    16
#define CHKLEN  (SEQ / NCHK)      // 128
#define NCH8    (BATCH * DIM / 8) // 4096 chains-of-8

// Scratch (device globals; no cudaMalloc allowed)
__device__ __half g_act[(size_t)M_TOT * N_TOT];   // 384 MB fp16 gates
__device__ float  g_Xr[(size_t)M_TOT * K_TOT];    // 256 MB tf32-rounded X
__device__ float  g_Wr[(size_t)N_TOT * K_TOT];    // 12  MB tf32-rounded W
__device__ float  g_A [(size_t)NCHK * BATCH * DIM];  // per-chunk A = prod f
__device__ float  g_B [(size_t)NCHK * BATCH * DIM];  // per-chunk B
__device__ float  g_h0[(size_t)NCHK * BATCH * DIM];  // chunk entry states

// ---------------------------------------------------------------------------
// Helpers
// ---------------------------------------------------------------------------
__device__ __forceinline__ uint32_t smem_u32(const void* p) {
    uint32_t a;
    asm("{ .reg .u64 t; cvta.to.shared.u64 t, %1; cvt.u32.u64 %0, t; }"
        : "=r"(a) : "l"(p));
    return a;
}
__device__ __forceinline__ uint32_t tf32_rna(float x) {
    uint32_t r; asm("cvt.rna.tf32.f32 %0, %1;" : "=r"(r) : "f"(x)); return r;
}
__device__ __forceinline__ float rcp_fast(float x) {
    float r; asm("rcp.approx.f32 %0, %1;" : "=f"(r) : "f"(x)); return r;
}
__device__ __forceinline__ float sigmoid_f(float x) {
    return rcp_fast(1.0f + __expf(-x));
}
__device__ __forceinline__ float tanh_f(float x) {
    return 1.0f - 2.0f * rcp_fast(1.0f + __expf(2.0f * x));
}

__device__ __forceinline__ void cp_async16(uint32_t dst_smem, const void* src) {
    asm volatile("cp.async.cg.shared.global [%0], [%1], 16;"
                 :: "r"(dst_smem), "l"(src) : "memory");
}
__device__ __forceinline__ void cp_commit() {
    asm volatile("cp.async.commit_group;" ::: "memory");
}
template <int N>
__device__ __forceinline__ void cp_wait() {
    asm volatile("cp.async.wait_group %0;" :: "n"(N) : "memory");
}

// m16n8k8 tf32 HMMA (portable PTX, legal at compute_103)
__device__ __forceinline__ void mma_tf32(float* d,
                                         const uint32_t* a,
                                         const uint32_t* bb) {
    asm volatile(
        "mma.sync.aligned.m16n8k8.row.col.f32.tf32.tf32.f32 "
        "{%0,%1,%2,%3}, {%4,%5,%6,%7}, {%8,%9}, {%0,%1,%2,%3};\n"
        : "+f"(d[0]), "+f"(d[1]), "+f"(d[2]), "+f"(d[3])
        : "r"(a[0]), "r"(a[1]), "r"(a[2]), "r"(a[3]),
          "r"(bb[0]), "r"(bb[1]));
}

// ---------------------------------------------------------------------------
// Kernel 0: round fp32 -> tf32 (rna)
// ---------------------------------------------------------------------------
__global__ __launch_bounds__(256)
void round_tf32_kernel(const float* __restrict__ in, float* __restrict__ out, int n4)
{
    int i = blockIdx.x * blockDim.x + threadIdx.x;
    if (i >= n4) return;
    float4 v = ((const float4*)in)[i];
    float4 o;
    o.x = __uint_as_float(tf32_rna(v.x));
    o.y = __uint_as_float(tf32_rna(v.y));
    o.z = __uint_as_float(tf32_rna(v.z));
    o.w = __uint_as_float(tf32_rna(v.w));
    ((float4*)out)[i] = o;
}

// ---------------------------------------------------------------------------
// Kernel 1: cp.async 3-stage pipelined tf32 HMMA GEMM (R10 mainloop).
//   128 threads = 4 warps in 2(M) x 2(N); warp tile 64x64; 2 CTAs/SM.
//   Epilogue stores fp16 gates (halves store traffic).
// ---------------------------------------------------------------------------
__global__ __launch_bounds__(128, 2)
void gemm_hmma_kernel(const float* __restrict__ b)
{
    extern __shared__ __align__(16) char smem[];
    const uint32_t sbase = smem_u32(smem);

    const int tid = threadIdx.x;
    const int wid = tid >> 5;       // 0..3
    const int lid = tid & 31;
    const int lq  = lid >> 2;       // 0..7
    const int lr  = lid & 3;        // 0..3

    const int wm = (wid >> 1) * 64; // warp M offset: 0 / 64
    const int wn = (wid & 1) * 64;  // warp N offset: 0 / 64

    const int block_m = blockIdx.y * BM;
    const int block_n = blockIdx.x * BN;

    const float* Abase = g_Xr + (size_t)block_m * K_TOT;
    const float* Bbase = g_Wr + (size_t)block_n * K_TOT;

    float acc[4][8][4];
#pragma unroll
    for (int mt = 0; mt < 4; ++mt)
#pragma unroll
        for (int nt = 0; nt < 8; ++nt)
#pragma unroll
            for (int r = 0; r < 4; ++r) acc[mt][nt][r] = 0.0f;

#pragma unroll
    for (int p = 0; p < NSTAGE; ++p) {
        const int kcol = p * BK;
        const uint32_t a_s = sbase + p * A_STG_BYTES;
        const uint32_t b_s = sbase + SMEM_B_BASE + p * B_STG_BYTES;
#pragma unroll
        for (int i = 0; i < 8; ++i) {
            int pos = tid + i * 128;
            int r = pos >> 3, c4 = pos & 7;
            cp_async16(a_s + (uint32_t)(r * ASTRIDE + c4 * 4) * 4,
                       Abase + (size_t)r * K_TOT + kcol + c4 * 4);
        }
#pragma unroll
        for (int i = 0; i < 8; ++i) {
            int pos = tid + i * 128;
            int r = pos >> 3, c4 = pos & 7;
            cp_async16(b_s + (uint32_t)(r * ASTRIDE + c4 * 4) * 4,
                       Bbase + (size_t)r * K_TOT + kcol + c4 * 4);
        }
        cp_commit();
    }

    for (int c = 0; c < NCHUNK; ++c) {
        const int buf = c % NSTAGE;
        cp_wait<NSTAGE - 1>();
        __syncthreads();

        const uint32_t* As = (const uint32_t*)(smem + buf * A_STG_BYTES);
        const uint32_t* Bs = (const uint32_t*)(smem + SMEM_B_BASE + buf * B_STG_BYTES);

#pragma unroll
        for (int ks = 0; ks < 4; ++ks) {
            const int k0 = ks * 8;
            uint32_t afrag[4][4], bfrag[8][2];
#pragma unroll
            for (int mt = 0; mt < 4; ++mt) {
                int base = (wm + mt * 16 + lq) * ASTRIDE + k0 + lr;
                afrag[mt][0] = As[base];
                afrag[mt][1] = As[base + 8 * ASTRIDE];
                afrag[mt][2] = As[base + 4];
                afrag[mt][3] = As[base + 8 * ASTRIDE + 4];
            }
#pragma unroll
            for (int nt = 0; nt < 8; ++nt) {
                int base = (wn + nt * 8 + lq) * ASTRIDE + k0 + lr;
                bfrag[nt][0] = Bs[base];
                bfrag[nt][1] = Bs[base + 4];
            }
#pragma unroll
            for (int mt = 0; mt < 4; ++mt)
#pragma unroll
                for (int nt = 0; nt < 8; ++nt)
                    mma_tf32(acc[mt][nt], afrag[mt], bfrag[nt]);
        }

        __syncthreads();

        if (c + NSTAGE < NCHUNK) {
            const int kcol = (c + NSTAGE) * BK;
            const uint32_t a_s = sbase + buf * A_STG_BYTES;
            const uint32_t b_s = sbase + SMEM_B_BASE + buf * B_STG_BYTES;
#pragma unroll
            for (int i = 0; i < 8; ++i) {
                int pos = tid + i * 128;
                int r = pos >> 3, c4 = pos & 7;
                cp_async16(a_s + (uint32_t)(r * ASTRIDE + c4 * 4) * 4,
                           Abase + (size_t)r * K_TOT + kcol + c4 * 4);
            }
#pragma unroll
            for (int i = 0; i < 8; ++i) {
                int pos = tid + i * 128;
                int r = pos >> 3, c4 = pos & 7;
                cp_async16(b_s + (uint32_t)(r * ASTRIDE + c4 * 4) * 4,
                           Bbase + (size_t)r * K_TOT + kcol + c4 * 4);
            }
        }
        cp_commit();
    }

    // ---- epilogue: bias + activation -> fp16 gates ----
    const bool is_tanh = (block_n < DIM);   // BN=128 divides DIM

#pragma unroll
    for (int nt = 0; nt < 8; ++nt) {
        const int gc = block_n + wn + nt * 8 + 2 * lr;   // even
        const float b0 = __ldg(&b[gc]);
        const float b1 = __ldg(&b[gc + 1]);
#pragma unroll
        for (int mt = 0; mt < 4; ++mt) {
            const int gm0 = block_m + wm + mt * 16 + lq;
            const int gm1 = gm0 + 8;
            float v00 = acc[mt][nt][0] + b0;
            float v01 = acc[mt][nt][1] + b1;
            float v10 = acc[mt][nt][2] + b0;
            float v11 = acc[mt][nt][3] + b1;
            float a00, a01, a10, a11;
            if (is_tanh) {
                a00 = tanh_f(v00); a01 = tanh_f(v01);
                a10 = tanh_f(v10); a11 = tanh_f(v11);
            } else {
                a00 = sigmoid_f(v00); a01 = sigmoid_f(v01);
                a10 = sigmoid_f(v10); a11 = sigmoid_f(v11);
            }
            *(__half2*)(&g_act[(size_t)gm0 * N_TOT + gc]) = __floats2half2_rn(a00, a01);
            *(__half2*)(&g_act[(size_t)gm1 * N_TOT + gc]) = __floats2half2_rn(a10, a11);
        }
    }
}

// ---------------------------------------------------------------------------
// Scan pass 1: per (chunk, 8-feature chain) affine map: h_out = A*h_in + B.
// Gates read as uint4 (8 fp16), math in fp32.
// ---------------------------------------------------------------------------
__global__ __launch_bounds__(128)
void scan_part1(void)
{
    const int g   = blockIdx.x * 128 + threadIdx.x;   // 0 .. NCHK*NCH8-1
    const int chk = g >> 12;                          // /4096
    const int fc  = g & (NCH8 - 1);                   // chain-of-8 index
    const int bb  = fc >> 7;                          // batch
    const int dh  = fc & 127;                         // 8-feature group in DIM

    const uint4* __restrict__ act8 = (const uint4*)g_act;  // 8 halves per uint4
    // row length in uint4 units: N_TOT/8 = 384; z at +dh, f at +128+dh

    float A[8], B[8];
#pragma unroll
    for (int j = 0; j < 8; ++j) { A[j] = 1.0f; B[j] = 0.0f; }

    const int s0 = chk * CHKLEN;
#pragma unroll 2
    for (int s = s0; s < s0 + CHKLEN; ++s) {
        const size_t row = (size_t)(s * BATCH + bb) * 384;
        uint4 zq = act8[row + dh];
        uint4 fq = act8[row + 128 + dh];
        const __half2* zp = (const __half2*)&zq;
        const __half2* fp = (const __half2*)&fq;
#pragma unroll
        for (int p = 0; p < 4; ++p) {
            float2 z2 = __half22float2(zp[p]);
            float2 f2 = __half22float2(fp[p]);
            A[2*p]   *= f2.x;
            A[2*p+1] *= f2.y;
            B[2*p]   = fmaf(f2.x, B[2*p]   - z2.x, z2.x);
            B[2*p+1] = fmaf(f2.y, B[2*p+1] - z2.y, z2.y);
        }
    }
    float* Adst = &g_A[(size_t)chk * (BATCH * DIM) + fc * 8];
    float* Bdst = &g_B[(size_t)chk * (BATCH * DIM) + fc * 8];
    *(float4*)(Adst)     = make_float4(A[0], A[1], A[2], A[3]);
    *(float4*)(Adst + 4) = make_float4(A[4], A[5], A[6], A[7]);
    *(float4*)(Bdst)     = make_float4(B[0], B[1], B[2], B[3]);
    *(float4*)(Bdst + 4) = make_float4(B[4], B[5], B[6], B[7]);
}

// ---------------------------------------------------------------------------
// Scan pass 2: compose chunk maps sequentially -> entry state h0 per chunk
// ---------------------------------------------------------------------------
__global__ __launch_bounds__(128)
void scan_part2(const float* __restrict__ hidden)
{
    const int fc = blockIdx.x * 128 + threadIdx.x;    // 0..4095
    float h[8];
    {
        float4 h0 = ((const float4*)hidden)[fc * 2];
        float4 h1 = ((const float4*)hidden)[fc * 2 + 1];
        h[0]=h0.x; h[1]=h0.y; h[2]=h0.z; h[3]=h0.w;
        h[4]=h1.x; h[5]=h1.y; h[6]=h1.z; h[7]=h1.w;
    }

#pragma unroll
    for (int c = 0; c < NCHK; ++c) {
        float* dst = &g_h0[(size_t)c * (BATCH * DIM) + fc * 8];
        *(float4*)(dst)     = make_float4(h[0], h[1], h[2], h[3]);
        *(float4*)(dst + 4) = make_float4(h[4], h[5], h[6], h[7]);
        const float* Ap = &g_A[(size_t)c * (BATCH * DIM) + fc * 8];
        const float* Bp = &g_B[(size_t)c * (BATCH * DIM) + fc * 8];
#pragma unroll
        for (int j = 0; j < 8; ++j)
            h[j] = fmaf(Ap[j], h[j], Bp[j]);
    }
}

// ---------------------------------------------------------------------------
// Scan pass 3: rerun recurrence per chunk from h0, write H = o*h (+ h_n)
// ---------------------------------------------------------------------------
__global__ __launch_bounds__(128)
void scan_part3(float* __restrict__ out)
{
    const int g   = blockIdx.x * 128 + threadIdx.x;
    const int chk = g >> 12;
    const int fc  = g & (NCH8 - 1);
    const int bb  = fc >> 7;
    const int dh  = fc & 127;

    const uint4* __restrict__ act8 = (const uint4*)g_act;
    float4* __restrict__ H4  = (float4*)out;
    float4* __restrict__ hn4 = (float4*)(out + (size_t)SEQ * BATCH * DIM);

    float h[8];
    {
        const float* src = &g_h0[(size_t)chk * (BATCH * DIM) + fc * 8];
        float4 a = *(const float4*)(src);
        float4 c = *(const float4*)(src + 4);
        h[0]=a.x; h[1]=a.y; h[2]=a.z; h[3]=a.w;
        h[4]=c.x; h[5]=c.y; h[6]=c.z; h[7]=c.w;
    }

    const int s0 = chk * CHKLEN;
#pragma unroll 2
    for (int s = s0; s < s0 + CHKLEN; ++s) {
        const size_t row = (size_t)(s * BATCH + bb) * 384;
        uint4 zq = act8[row + dh];
        uint4 fq = act8[row + 128 + dh];
        uint4 oq = act8[row + 256 + dh];
        const __half2* zp = (const __half2*)&zq;
        const __half2* fp = (const __half2*)&fq;
        const __half2* op = (const __half2*)&oq;
        float r[8];
#pragma unroll
        for (int p = 0; p < 4; ++p) {
            float2 z2 = __half22float2(zp[p]);
            float2 f2 = __half22float2(fp[p]);
            float2 o2 = __half22float2(op[p]);
            h[2*p]   = fmaf(f2.x, h[2*p]   - z2.x, z2.x);
            h[2*p+1] = fmaf(f2.y, h[2*p+1] - z2.y, z2.y);
            r[2*p]   = o2.x * h[2*p];
            r[2*p+1] = o2.y * h[2*p+1];
        }
        const size_t hbase = ((size_t)(s * BATCH + bb) * DIM + dh * 8) >> 2;
        H4[hbase]     = make_float4(r[0], r[1], r[2], r[3]);
        H4[hbase + 1] = make_float4(r[4], r[5], r[6], r[7]);
    }
    if (chk == NCHK - 1) {
        hn4[fc * 2]     = make_float4(h[0], h[1], h[2], h[3]);
        hn4[fc * 2 + 1] = make_float4(h[4], h[5], h[6], h[7]);
    }
}

// ---------------------------------------------------------------------------
extern "C" void kernel_launch(void* const* d_in, const int* in_sizes, int n_in,
                              void* d_out, int out_size)
{
    const float* X      = (const float*)d_in[0];   // [2048, 32, 1024]
    const float* hidden = (const float*)d_in[1];   // [1, 32, 1024]
    const float* W      = (const float*)d_in[2];   // [3072, 1024]
    const float* b      = (const float*)d_in[3];   // [3072]
    float* out = (float*)d_out;

    cudaFuncSetAttribute(gemm_hmma_kernel,
                         cudaFuncAttributeMaxDynamicSharedMemorySize,
                         SMEM_BYTES);

    float* Xr; float* Wr;
    cudaGetSymbolAddress((void**)&Xr, g_Xr);
    cudaGetSymbolAddress((void**)&Wr, g_Wr);

    // round inputs to tf32 (rna)
    {
        int n4x = (M_TOT * K_TOT) / 4;
        round_tf32_kernel<<<n4x / 256, 256>>>(X, Xr, n4x);
        int n4w = (N_TOT * K_TOT) / 4;
        round_tf32_kernel<<<n4w / 256, 256>>>(W, Wr, n4w);
    }

    dim3 grid(N_TOT / BN, M_TOT / BM);   // (24, 512)
    gemm_hmma_kernel<<<grid, 128, SMEM_BYTES>>>(b);

    scan_part1<<<(NCHK * NCH8) / 128, 128>>>();
    scan_part2<<<NCH8 / 128, 128>>>(hidden);
    scan_part3<<<(NCHK * NCH8) / 128, 128>>>(out);
}